// round 5
// baseline (speedup 1.0000x reference)
#include <cuda_runtime.h>

#define Bc   2
#define Mq   16384
#define Np   4096
#define Cin  128
#define CsF  256
#define DoC  128
#define NCOLS (Bc*Mq)
#define NBLK  512            // gemm1/gemm2 grid
#define PH   2048
#define LDW  136             // 128-wide k-major W rows, pad 8
#define LDX1 72              // 64-wide X rows, pad 8 (gemm1/gemm2)
#define LDXP 40              // 32-wide X rows, pad 8 (gemmP)
// per-stage float layout (gemm1/2): Whi[0,2176) Wlo[2176,4352) X[4352,5504)
#define STG1 5504
// gemmP: Whi[0,2176) Wlo[2176,4352) X[4352,4992)
#define STGP 4992

// ---------------- scratch (device globals) ----------------
__device__ __align__(16) float d_W1hi[384*128];
__device__ __align__(16) float d_W1lo[384*128];
__device__ __align__(16) float d_W2hi[128*128];
__device__ __align__(16) float d_W2lo[128*128];
__device__ __align__(16) float d_P  [Bc*Np*DoC];
__device__ float d_cd[Bc*Mq*6];
__device__ int   d_ci[Bc*Mq*6];
__device__ int   d_idx[Bc*Mq*3];
__device__ float d_w  [Bc*Mq*3];
__device__ __align__(16) float d_z1 [Bc*DoC*Mq];
__device__ __align__(16) float d_z2 [Bc*DoC*Mq];
__device__ float d_psum[NBLK*DoC];
__device__ float d_psq [NBLK*DoC];
__device__ float d_bn1[2*DoC];
__device__ float d_bn2[2*DoC];

// ---------------- helpers ----------------
__device__ __forceinline__ void cp16(float* s, const float* g) {
  unsigned sa = (unsigned)__cvta_generic_to_shared(s);
  asm volatile("cp.async.cg.shared.global [%0], [%1], 16;\n" :: "r"(sa), "l"(g));
}
__device__ __forceinline__ void cp_commit() { asm volatile("cp.async.commit_group;\n"); }
template<int N> __device__ __forceinline__ void cp_wait() {
  asm volatile("cp.async.wait_group %0;\n" :: "n"(N));
}
__device__ __forceinline__ void mma8(float* d, const unsigned* a, const unsigned* b) {
  asm("mma.sync.aligned.m16n8k8.row.col.f32.tf32.tf32.f32 "
      "{%0,%1,%2,%3}, {%4,%5,%6,%7}, {%8,%9}, {%0,%1,%2,%3};"
      : "+f"(d[0]), "+f"(d[1]), "+f"(d[2]), "+f"(d[3])
      : "r"(a[0]), "r"(a[1]), "r"(a[2]), "r"(a[3]), "r"(b[0]), "r"(b[1]));
}
__device__ __forceinline__ void split3(float x, unsigned& hi, unsigned& lo) {
  hi = __float_as_uint(x) & 0xffffe000u;
  float r = x - __uint_as_float(hi);
  lo = __float_as_uint(r) & 0xffffe000u;
}

// 3xTF32 over a 16-k chunk. Whp/Wlp: precomputed hi/lo, k-major [16][LDW],
// pre-offset by warp's ob. Xp: raw fp32 [16][LX], pre-offset by warp's mb.
// Warp computes 32o x (8*NT)m. acc[2][NT][4].
template<int NT, int LX>
__device__ __forceinline__ void cmma(const float* Whp, const float* Wlp, const float* Xp,
                                     int g, int tg, float (&acc)[2][NT][4]) {
  #pragma unroll
  for (int s = 0; s < 2; s++) {
    int kr = s * 8;
    unsigned ah[2][4], al[2][4];
    const float* h0 = Whp + (kr+tg)*LDW;
    const float* h1 = Whp + (kr+tg+4)*LDW;
    const float* l0 = Wlp + (kr+tg)*LDW;
    const float* l1 = Wlp + (kr+tg+4)*LDW;
    #pragma unroll
    for (int i = 0; i < 2; i++) {
      int o0 = 16*i + g;
      ah[i][0] = __float_as_uint(h0[o0]);
      ah[i][1] = __float_as_uint(h0[o0+8]);
      ah[i][2] = __float_as_uint(h1[o0]);
      ah[i][3] = __float_as_uint(h1[o0+8]);
      al[i][0] = __float_as_uint(l0[o0]);
      al[i][1] = __float_as_uint(l0[o0+8]);
      al[i][2] = __float_as_uint(l1[o0]);
      al[i][3] = __float_as_uint(l1[o0+8]);
    }
    #pragma unroll
    for (int n = 0; n < NT; n++) {
      float x0 = Xp[(kr+tg)*LX + 8*n + g];
      float x1 = Xp[(kr+tg+4)*LX + 8*n + g];
      unsigned bh[2], bl[2];
      split3(x0, bh[0], bl[0]);
      split3(x1, bh[1], bl[1]);
      mma8(acc[0][n], al[0], bh);
      mma8(acc[0][n], ah[0], bl);
      mma8(acc[0][n], ah[0], bh);
      mma8(acc[1][n], al[1], bh);
      mma8(acc[1][n], ah[1], bl);
      mma8(acc[1][n], ah[1], bh);
    }
  }
}

// Same with relu(bn(.)) applied to X before split (gemm2). sa/sd indexed by absolute k.
template<int NT, int LX>
__device__ __forceinline__ void cmma_bn(const float* Whp, const float* Wlp, const float* Xp,
                                        const float* sa, const float* sd, int kc,
                                        int g, int tg, float (&acc)[2][NT][4]) {
  #pragma unroll
  for (int s = 0; s < 2; s++) {
    int kr = s * 8;
    float A0 = sa[kc+kr+tg],   D0 = sd[kc+kr+tg];
    float A1 = sa[kc+kr+tg+4], D1 = sd[kc+kr+tg+4];
    unsigned ah[2][4], al[2][4];
    const float* h0 = Whp + (kr+tg)*LDW;
    const float* h1 = Whp + (kr+tg+4)*LDW;
    const float* l0 = Wlp + (kr+tg)*LDW;
    const float* l1 = Wlp + (kr+tg+4)*LDW;
    #pragma unroll
    for (int i = 0; i < 2; i++) {
      int o0 = 16*i + g;
      ah[i][0] = __float_as_uint(h0[o0]);
      ah[i][1] = __float_as_uint(h0[o0+8]);
      ah[i][2] = __float_as_uint(h1[o0]);
      ah[i][3] = __float_as_uint(h1[o0+8]);
      al[i][0] = __float_as_uint(l0[o0]);
      al[i][1] = __float_as_uint(l0[o0+8]);
      al[i][2] = __float_as_uint(l1[o0]);
      al[i][3] = __float_as_uint(l1[o0+8]);
    }
    #pragma unroll
    for (int n = 0; n < NT; n++) {
      float x0 = fmaxf(fmaf(A0, Xp[(kr+tg)*LX + 8*n + g], D0), 0.0f);
      float x1 = fmaxf(fmaf(A1, Xp[(kr+tg+4)*LX + 8*n + g], D1), 0.0f);
      unsigned bh[2], bl[2];
      split3(x0, bh[0], bl[0]);
      split3(x1, bh[1], bl[1]);
      mma8(acc[0][n], al[0], bh);
      mma8(acc[0][n], ah[0], bl);
      mma8(acc[0][n], ah[0], bh);
      mma8(acc[1][n], al[1], bh);
      mma8(acc[1][n], ah[1], bl);
      mma8(acc[1][n], ah[1], bh);
    }
  }
}

// ---------------- W transpose + hi/lo split ----------------
__global__ __launch_bounds__(256) void split_w_kernel(
    const float* __restrict__ W1, const float* __restrict__ W2) {
  int e = blockIdx.x * 256 + threadIdx.x;   // 65536
  float w; float* hi; float* lo; int idx;
  if (e < 384*128) {
    int k = e >> 7, o = e & 127;
    w = W1[o*384 + k]; hi = d_W1hi; lo = d_W1lo; idx = e;
  } else {
    int e2 = e - 384*128;
    int k = e2 >> 7, o = e2 & 127;
    w = W2[o*128 + k]; hi = d_W2hi; lo = d_W2lo; idx = e2;
  }
  unsigned h, l;
  split3(w, h, l);
  hi[idx] = __uint_as_float(h);
  lo[idx] = __uint_as_float(l);
}

// ---------------- 3-NN: 2 queries/thread, point dim split in 2 ----------------
__global__ __launch_bounds__(256) void knn_kernel(
    const float* __restrict__ xyz, const float* __restrict__ sub_xyz) {
  __shared__ float4 pts[PH];
  int bx = blockIdx.x;                      // 128 blocks
  int b    = bx >> 6;
  int half = (bx >> 5) & 1;
  int m0   = ((bx & 31) << 9) + threadIdx.x;
  const float* sp = sub_xyz + (size_t)b * 3 * Np + half * PH;
  for (int i = threadIdx.x; i < PH; i += 256) {
    float px = sp[i], py = sp[Np + i], pz = sp[2*Np + i];
    pts[i] = make_float4(px, py, pz, fmaf(px, px, fmaf(py, py, pz*pz)));
  }
  __syncthreads();
  const float* qp = xyz + (size_t)b * 3 * Mq;
  int mA = m0, mB = m0 + 256;
  float nxA = -2.f*qp[mA], nyA = -2.f*qp[Mq+mA], nzA = -2.f*qp[2*Mq+mA];
  float nxB = -2.f*qp[mB], nyB = -2.f*qp[Mq+mB], nzB = -2.f*qp[2*Mq+mB];

  float a0=3.4e38f,a1=3.4e38f,a2=3.4e38f; int ja0=0,ja1=0,ja2=0;
  float b0=3.4e38f,b1=3.4e38f,b2=3.4e38f; int jb0=0,jb1=0,jb2=0;
  #pragma unroll 4
  for (int i = 0; i < PH; i++) {
    float4 p = pts[i];
    float eA = fmaf(nxA, p.x, fmaf(nyA, p.y, fmaf(nzA, p.z, p.w)));
    float eB = fmaf(nxB, p.x, fmaf(nyB, p.y, fmaf(nzB, p.z, p.w)));
    if (eA < a2) {
      if (eA < a1) {
        a2 = a1; ja2 = ja1;
        if (eA < a0) { a1 = a0; ja1 = ja0; a0 = eA; ja0 = i; }
        else         { a1 = eA; ja1 = i; }
      } else { a2 = eA; ja2 = i; }
    }
    if (eB < b2) {
      if (eB < b1) {
        b2 = b1; jb2 = jb1;
        if (eB < b0) { b1 = b0; jb1 = jb0; b0 = eB; jb0 = i; }
        else         { b1 = eB; jb1 = i; }
      } else { b2 = eB; jb2 = i; }
    }
  }
  int off = half * PH;
  size_t baseA = ((size_t)(b * Mq + mA) * 2 + half) * 3;
  d_cd[baseA+0]=a0; d_cd[baseA+1]=a1; d_cd[baseA+2]=a2;
  d_ci[baseA+0]=ja0+off; d_ci[baseA+1]=ja1+off; d_ci[baseA+2]=ja2+off;
  size_t baseB = ((size_t)(b * Mq + mB) * 2 + half) * 3;
  d_cd[baseB+0]=b0; d_cd[baseB+1]=b1; d_cd[baseB+2]=b2;
  d_ci[baseB+0]=jb0+off; d_ci[baseB+1]=jb1+off; d_ci[baseB+2]=jb2+off;
}

// ---------------- merge 6 candidates ----------------
__global__ __launch_bounds__(256) void knn_merge_kernel(const float* __restrict__ xyz) {
  int g = blockIdx.x * 256 + threadIdx.x;
  int b = g >> 14, m = g & (Mq - 1);
  const float* qp = xyz + (size_t)b * 3 * Mq;
  float qx = qp[m], qy = qp[Mq + m], qz = qp[2*Mq + m];
  float qq = fmaf(qx, qx, fmaf(qy, qy, qz*qz));
  float c0 = 3.4e38f, c1 = 3.4e38f, c2 = 3.4e38f;
  int j0 = 0, j1 = 0, j2 = 0;
  size_t base = (size_t)g * 6;
  #pragma unroll
  for (int t = 0; t < 6; t++) {
    float e = d_cd[base + t];
    int  id = d_ci[base + t];
    if (e < c2) {
      if (e < c1) {
        c2 = c1; j2 = j1;
        if (e < c0) { c1 = c0; j1 = j0; c0 = e; j0 = id; }
        else        { c1 = e; j1 = id; }
      } else { c2 = e; j2 = id; }
    }
  }
  float d0  = fmaxf(c0 + qq, 0.0f);
  float d1  = fmaxf(c1 + qq, 0.0f);
  float d2v = fmaxf(c2 + qq, 0.0f);
  float w0 = 1.0f / (d0 + 1e-8f);
  float w1 = 1.0f / (d1 + 1e-8f);
  float w2 = 1.0f / (d2v + 1e-8f);
  float inv = 1.0f / (w0 + w1 + w2);
  d_idx[g*3+0]=j0; d_idx[g*3+1]=j1; d_idx[g*3+2]=j2;
  d_w[g*3+0]=w0*inv; d_w[g*3+1]=w1*inv; d_w[g*3+2]=w2*inv;
}

// ---------------- P = W1[:,128:384] @ sub_x, block 128o x 32n, grid 256 ----------------
__global__ __launch_bounds__(256, 2) void gemmP_kernel(const float* __restrict__ sub_x) {
  extern __shared__ float smem[];
  int tid = threadIdx.x;
  int lane = tid & 31, warp = tid >> 5;
  int g = lane >> 2, tg = lane & 3;
  int ob = (warp & 3) * 32, mb = (warp >> 2) * 16;
  int bx = blockIdx.x;
  int b = bx >> 7, n0 = (bx & 127) << 5;
  const float* xb = sub_x + (size_t)b * CsF * Np;

  float acc[2][2][4];
  #pragma unroll
  for (int i = 0; i < 2; i++)
    #pragma unroll
    for (int n = 0; n < 2; n++)
      #pragma unroll
      for (int r = 0; r < 4; r++) acc[i][n][r] = 0.0f;

  auto load_chunk = [&](int kc, int s) {
    float* st = smem + s*STGP;
    #pragma unroll
    for (int k = 0; k < 2; k++) {
      int e4 = tid + k*256, kk = e4 >> 5, c = (e4 & 31) << 2;
      size_t go = (size_t)(Cin + kc + kk)*128 + c;
      cp16(st + kk*LDW + c,        d_W1hi + go);
      cp16(st + 2176 + kk*LDW + c, d_W1lo + go);
    }
    if (tid < 128) {
      int kk = tid >> 3, c = (tid & 7) << 2;
      cp16(st + 4352 + kk*LDXP + c, xb + (size_t)(kc + kk)*Np + n0 + c);
    }
  };
  load_chunk(0, 0); cp_commit();
  for (int ch = 0; ch < 16; ch++) {
    if (ch < 15) { load_chunk((ch+1)*16, (ch+1)&1); cp_commit(); cp_wait<1>(); }
    else         { cp_wait<0>(); }
    __syncthreads();
    const float* st = smem + (ch&1)*STGP;
    cmma<2, LDXP>(st + ob, st + 2176 + ob, st + 4352 + mb, g, tg, acc);
    __syncthreads();
  }

  // stage Z[o][n] (stride 40), then store P[n][o]
  float* Zs = smem;
  #pragma unroll
  for (int i = 0; i < 2; i++)
    #pragma unroll
    for (int n = 0; n < 2; n++) {
      int o = ob + 16*i + g;
      int m = mb + 8*n + 2*tg;
      *(float2*)&Zs[(size_t)o*40 + m]     = make_float2(acc[i][n][0], acc[i][n][1]);
      *(float2*)&Zs[(size_t)(o+8)*40 + m] = make_float2(acc[i][n][2], acc[i][n][3]);
    }
  __syncthreads();
  int nl = tid & 31, oh = tid >> 5;
  float* dst = d_P + ((size_t)b * Np + n0 + nl) * 128;
  #pragma unroll
  for (int o = oh*16; o < oh*16 + 16; o += 4) {
    float4 v = make_float4(Zs[(o+0)*40 + nl], Zs[(o+1)*40 + nl],
                           Zs[(o+2)*40 + nl], Zs[(o+3)*40 + nl]);
    *(float4*)(dst + o) = v;
  }
}

// ---------------- z1 = W1a @ x + gather(P), + stats; block 128o x 64m, grid 512 ----------------
__global__ __launch_bounds__(256, 2) void gemm1_kernel(const float* __restrict__ x) {
  extern __shared__ float smem[];
  int*   sidx = (int*)(smem + 2*STG1);       // 192
  float* sw   = smem + 2*STG1 + 192;         // 192
  int tid = threadIdx.x;
  int lane = tid & 31, warp = tid >> 5;
  int g = lane >> 2, tg = lane & 3;
  int ob = (warp & 3) * 32, mb = (warp >> 2) * 32;
  int bx = blockIdx.x;
  int b = bx >> 8, m0 = (bx & 255) << 6;
  const float* xb = x + (size_t)b * Cin * Mq;

  if (tid < 192) {
    size_t cb = ((size_t)(b * Mq + m0)) * 3 + tid;
    sidx[tid] = d_idx[cb]; sw[tid] = d_w[cb];
  }

  float acc[2][4][4];
  #pragma unroll
  for (int i = 0; i < 2; i++)
    #pragma unroll
    for (int n = 0; n < 4; n++)
      #pragma unroll
      for (int r = 0; r < 4; r++) acc[i][n][r] = 0.0f;

  auto load_chunk = [&](int kc, int s) {
    float* st = smem + s*STG1;
    #pragma unroll
    for (int k = 0; k < 2; k++) {
      int e4 = tid + k*256, kk = e4 >> 5, c = (e4 & 31) << 2;
      size_t go = (size_t)(kc + kk)*128 + c;
      cp16(st + kk*LDW + c,        d_W1hi + go);
      cp16(st + 2176 + kk*LDW + c, d_W1lo + go);
    }
    {
      int kk = tid >> 4, c = (tid & 15) << 2;
      cp16(st + 4352 + kk*LDX1 + c, xb + (size_t)(kc + kk)*Mq + m0 + c);
    }
  };
  load_chunk(0, 0); cp_commit();
  for (int ch = 0; ch < 8; ch++) {
    if (ch < 7) { load_chunk((ch+1)*16, (ch+1)&1); cp_commit(); cp_wait<1>(); }
    else        { cp_wait<0>(); }
    __syncthreads();
    const float* st = smem + (ch&1)*STG1;
    cmma<4, LDX1>(st + ob, st + 2176 + ob, st + 4352 + mb, g, tg, acc);
    __syncthreads();
  }

  // acc -> Zs[o][m] (stride 72, 128x64)
  float* Zs = smem;
  #pragma unroll
  for (int i = 0; i < 2; i++)
    #pragma unroll
    for (int n = 0; n < 4; n++) {
      int o = ob + 16*i + g;
      int m = mb + 8*n + 2*tg;
      *(float2*)&Zs[(size_t)o*LDX1 + m]     = make_float2(acc[i][n][0], acc[i][n][1]);
      *(float2*)&Zs[(size_t)(o+8)*LDX1 + m] = make_float2(acc[i][n][2], acc[i][n][3]);
    }
  __syncthreads();

  // gather-interpolate + store z1 + write back for stats
  int mcol = tid & 63, oq = tid >> 6;    // 4 channel-quarters of 32
  int i0 = sidx[mcol*3+0], i1 = sidx[mcol*3+1], i2 = sidx[mcol*3+2];
  float w0 = sw[mcol*3+0], w1 = sw[mcol*3+1], w2 = sw[mcol*3+2];
  const float* P0 = d_P + ((size_t)b*Np + i0) * 128;
  const float* P1 = d_P + ((size_t)b*Np + i1) * 128;
  const float* P2 = d_P + ((size_t)b*Np + i2) * 128;
  float* zb = d_z1 + (size_t)b * DoC * Mq + m0 + mcol;
  #pragma unroll 2
  for (int o = oq*32; o < oq*32 + 32; o += 4) {
    float4 q0 = *(const float4*)(P0 + o);
    float4 q1 = *(const float4*)(P1 + o);
    float4 q2 = *(const float4*)(P2 + o);
    float v0 = Zs[(o+0)*LDX1 + mcol] + w0*q0.x + w1*q1.x + w2*q2.x;
    float v1 = Zs[(o+1)*LDX1 + mcol] + w0*q0.y + w1*q1.y + w2*q2.y;
    float v2 = Zs[(o+2)*LDX1 + mcol] + w0*q0.z + w1*q1.z + w2*q2.z;
    float v3 = Zs[(o+3)*LDX1 + mcol] + w0*q0.w + w1*q1.w + w2*q2.w;
    zb[(size_t)(o+0)*Mq] = v0;
    zb[(size_t)(o+1)*Mq] = v1;
    zb[(size_t)(o+2)*Mq] = v2;
    zb[(size_t)(o+3)*Mq] = v3;
    Zs[(o+0)*LDX1 + mcol] = v0;
    Zs[(o+1)*LDX1 + mcol] = v1;
    Zs[(o+2)*LDX1 + mcol] = v2;
    Zs[(o+3)*LDX1 + mcol] = v3;
  }
  __syncthreads();
  if (tid < 128) {
    const float* zr = &Zs[(size_t)tid * LDX1];
    float s = 0.0f, q = 0.0f;
    #pragma unroll 4
    for (int m = 0; m < 64; m += 4) {
      float4 v = *(const float4*)(zr + m);
      s += v.x + v.y + v.z + v.w;
      q += v.x*v.x + v.y*v.y + v.z*v.z + v.w*v.w;
    }
    d_psum[bx * DoC + tid] = s;
    d_psq [bx * DoC + tid] = q;
  }
}

// ---------------- BN finalize ----------------
__global__ void bn_finalize_kernel(const float* __restrict__ g,
                                   const float* __restrict__ bias, int which) {
  __shared__ float ss[512], sq[512];
  int tid = threadIdx.x;
  int ch = tid & 127, part = tid >> 7;
  float s = 0.0f, q = 0.0f;
  for (int blk = part; blk < NBLK; blk += 4) {
    s += d_psum[blk * DoC + ch];
    q += d_psq [blk * DoC + ch];
  }
  ss[tid] = s; sq[tid] = q;
  __syncthreads();
  if (tid < 128) {
    float S = ss[tid] + ss[tid+128] + ss[tid+256] + ss[tid+384];
    float Q = sq[tid] + sq[tid+128] + sq[tid+256] + sq[tid+384];
    const float invN = 1.0f / (float)NCOLS;
    float mean = S * invN;
    float var  = Q * invN - mean * mean;
    float rstd = rsqrtf(var + 1e-5f);
    float a = g[tid] * rstd;
    float d = bias[tid] - mean * a;
    float* ab = which ? d_bn2 : d_bn1;
    ab[tid] = a; ab[DoC + tid] = d;
  }
}

// ---------------- z2 = W2 @ relu(bn1(z1)), + stats; block 128o x 64m, grid 512 ----------------
__global__ __launch_bounds__(256, 2) void gemm2_kernel() {
  extern __shared__ float smem[];
  float* sa = smem + 2*STG1;         // 128
  float* sd = smem + 2*STG1 + 128;   // 128
  int tid = threadIdx.x;
  int lane = tid & 31, warp = tid >> 5;
  int g = lane >> 2, tg = lane & 3;
  int ob = (warp & 3) * 32, mb = (warp >> 2) * 32;
  int bx = blockIdx.x;
  int b = bx >> 8, m0 = (bx & 255) << 6;
  if (tid < 128) { sa[tid] = d_bn1[tid]; sd[tid] = d_bn1[DoC + tid]; }
  const float* zb0 = d_z1 + (size_t)b * DoC * Mq;

  float acc[2][4][4];
  #pragma unroll
  for (int i = 0; i < 2; i++)
    #pragma unroll
    for (int n = 0; n < 4; n++)
      #pragma unroll
      for (int r = 0; r < 4; r++) acc[i][n][r] = 0.0f;

  auto load_chunk = [&](int kc, int s) {
    float* st = smem + s*STG1;
    #pragma unroll
    for (int k = 0; k < 2; k++) {
      int e4 = tid + k*256, kk = e4 >> 5, c = (e4 & 31) << 2;
      size_t go = (size_t)(kc + kk)*128 + c;
      cp16(st + kk*LDW + c,        d_W2hi + go);
      cp16(st + 2176 + kk*LDW + c, d_W2lo + go);
    }
    {
      int kk = tid >> 4, c = (tid & 15) << 2;
      cp16(st + 4352 + kk*LDX1 + c, zb0 + (size_t)(kc + kk)*Mq + m0 + c);
    }
  };
  load_chunk(0, 0); cp_commit();
  for (int ch = 0; ch < 8; ch++) {
    if (ch < 7) { load_chunk((ch+1)*16, (ch+1)&1); cp_commit(); cp_wait<1>(); }
    else        { cp_wait<0>(); }
    __syncthreads();
    const float* st = smem + (ch&1)*STG1;
    cmma_bn<4, LDX1>(st + ob, st + 2176 + ob, st + 4352 + mb, sa, sd, ch*16, g, tg, acc);
    __syncthreads();
  }

  float* Zs = smem;
  #pragma unroll
  for (int i = 0; i < 2; i++)
    #pragma unroll
    for (int n = 0; n < 4; n++) {
      int o = ob + 16*i + g;
      int m = mb + 8*n + 2*tg;
      *(float2*)&Zs[(size_t)o*LDX1 + m]     = make_float2(acc[i][n][0], acc[i][n][1]);
      *(float2*)&Zs[(size_t)(o+8)*LDX1 + m] = make_float2(acc[i][n][2], acc[i][n][3]);
    }
  __syncthreads();

  int mcol = tid & 63, oq = tid >> 6;
  float* zb = d_z2 + (size_t)b * DoC * Mq + m0 + mcol;
  #pragma unroll 2
  for (int o = oq*32; o < oq*32 + 32; o += 4) {
    zb[(size_t)(o+0)*Mq] = Zs[(o+0)*LDX1 + mcol];
    zb[(size_t)(o+1)*Mq] = Zs[(o+1)*LDX1 + mcol];
    zb[(size_t)(o+2)*Mq] = Zs[(o+2)*LDX1 + mcol];
    zb[(size_t)(o+3)*Mq] = Zs[(o+3)*LDX1 + mcol];
  }
  __syncthreads();
  if (tid < 128) {
    const float* zr = &Zs[(size_t)tid * LDX1];
    float s = 0.0f, q = 0.0f;
    #pragma unroll 4
    for (int m = 0; m < 64; m += 4) {
      float4 v = *(const float4*)(zr + m);
      s += v.x + v.y + v.z + v.w;
      q += v.x*v.x + v.y*v.y + v.z*v.z + v.w*v.w;
    }
    d_psum[bx * DoC + tid] = s;
    d_psq [bx * DoC + tid] = q;
  }
}

// ---------------- out = relu(bn2(z2)) ----------------
__global__ __launch_bounds__(256) void final_kernel(float* __restrict__ out) {
  int e4 = blockIdx.x * 256 + threadIdx.x;
  int ch = (e4 >> 12) & 127;
  float a = d_bn2[ch], d = d_bn2[DoC + ch];
  float4 v = *((const float4*)d_z2 + e4);
  v.x = fmaxf(fmaf(a, v.x, d), 0.0f);
  v.y = fmaxf(fmaf(a, v.y, d), 0.0f);
  v.z = fmaxf(fmaf(a, v.z, d), 0.0f);
  v.w = fmaxf(fmaf(a, v.w, d), 0.0f);
  *((float4*)out + e4) = v;
}

// ---------------- launch ----------------
extern "C" void kernel_launch(void* const* d_in, const int* in_sizes, int n_in,
                              void* d_out, int out_size) {
  const float* x       = (const float*)d_in[0];
  const float* xyz     = (const float*)d_in[1];
  const float* sub_x   = (const float*)d_in[2];
  const float* sub_xyz = (const float*)d_in[3];
  const float* W1      = (const float*)d_in[4];
  const float* g1      = (const float*)d_in[5];
  const float* b1      = (const float*)d_in[6];
  const float* W2      = (const float*)d_in[7];
  const float* g2      = (const float*)d_in[8];
  const float* b2      = (const float*)d_in[9];
  float* out = (float*)d_out;

  split_w_kernel<<<256, 256>>>(W1, W2);
  knn_kernel<<<128, 256>>>(xyz, sub_xyz);
  knn_merge_kernel<<<128, 256>>>(xyz);
  gemmP_kernel<<<256, 256, STGP*2*4>>>(sub_x);            // 39936 B
  gemm1_kernel<<<512, 256, (2*STG1 + 384)*4>>>(x);        // 45568 B
  bn_finalize_kernel<<<1, 512>>>(g1, b1, 0);
  gemm2_kernel<<<512, 256, (2*STG1 + 256)*4>>>();         // 45056 B
  bn_finalize_kernel<<<1, 512>>>(g2, b2, 1);
  final_kernel<<<4096, 256>>>(out);
}

// round 6
// speedup vs baseline: 1.0078x; 1.0078x over previous
#include <cuda_runtime.h>

#define Bc   2
#define Mq   16384
#define Np   4096
#define Cin  128
#define CsF  256
#define DoC  128
#define NCOLS (Bc*Mq)
#define NBLK  256            // gemm1/gemm2 grid (stats blocks)
#define PH   2048
#define LDW  136             // 128-wide k-major rows, pad 8
// per-stage float layout: Whi[0,2176) Wlo[2176,4352) X[4352,6528)
#define STG  6528

// ---------------- scratch (device globals) ----------------
__device__ __align__(16) float d_W1hi[384*128];
__device__ __align__(16) float d_W1lo[384*128];
__device__ __align__(16) float d_W2hi[128*128];
__device__ __align__(16) float d_W2lo[128*128];
__device__ __align__(16) float d_P  [Bc*Np*DoC];
__device__ float d_cd[Bc*Mq*6];
__device__ int   d_ci[Bc*Mq*6];
__device__ int   d_idx[Bc*Mq*3];
__device__ float d_w  [Bc*Mq*3];
__device__ __align__(16) float d_z1 [Bc*DoC*Mq];
__device__ __align__(16) float d_z2 [Bc*DoC*Mq];
__device__ float d_psum[NBLK*DoC];
__device__ float d_psq [NBLK*DoC];
__device__ float d_bn1[2*DoC];
__device__ float d_bn2[2*DoC];

// ---------------- helpers ----------------
__device__ __forceinline__ void cp16(float* s, const float* g) {
  unsigned sa = (unsigned)__cvta_generic_to_shared(s);
  asm volatile("cp.async.cg.shared.global [%0], [%1], 16;\n" :: "r"(sa), "l"(g));
}
__device__ __forceinline__ void cp_commit() { asm volatile("cp.async.commit_group;\n"); }
template<int N> __device__ __forceinline__ void cp_wait() {
  asm volatile("cp.async.wait_group %0;\n" :: "n"(N));
}
__device__ __forceinline__ void mma8(float* d, const unsigned* a, const unsigned* b) {
  asm("mma.sync.aligned.m16n8k8.row.col.f32.tf32.tf32.f32 "
      "{%0,%1,%2,%3}, {%4,%5,%6,%7}, {%8,%9}, {%0,%1,%2,%3};"
      : "+f"(d[0]), "+f"(d[1]), "+f"(d[2]), "+f"(d[3])
      : "r"(a[0]), "r"(a[1]), "r"(a[2]), "r"(a[3]), "r"(b[0]), "r"(b[1]));
}
__device__ __forceinline__ void split3(float x, unsigned& hi, unsigned& lo) {
  hi = __float_as_uint(x) & 0xffffe000u;
  float r = x - __uint_as_float(hi);
  lo = __float_as_uint(r) & 0xffffe000u;
}

// 3xTF32 over a 16-k chunk. Whp/Wlp precomputed hi/lo tiles [16][LDW] pre-offset
// by warp's o-base; Xp raw fp32 [16][LDW] pre-offset by warp's m-base.
// Warp tile: 32o x 32m. acc[2][4][4].
__device__ __forceinline__ void cmma4(const float* Whp, const float* Wlp, const float* Xp,
                                      int g, int tg, float (&acc)[2][4][4]) {
  #pragma unroll
  for (int s = 0; s < 2; s++) {
    int kr = s * 8;
    unsigned ah[2][4], al[2][4];
    const float* h0 = Whp + (kr+tg)*LDW;
    const float* h1 = Whp + (kr+tg+4)*LDW;
    const float* l0 = Wlp + (kr+tg)*LDW;
    const float* l1 = Wlp + (kr+tg+4)*LDW;
    #pragma unroll
    for (int i = 0; i < 2; i++) {
      int o0 = 16*i + g;
      ah[i][0] = __float_as_uint(h0[o0]);
      ah[i][1] = __float_as_uint(h0[o0+8]);
      ah[i][2] = __float_as_uint(h1[o0]);
      ah[i][3] = __float_as_uint(h1[o0+8]);
      al[i][0] = __float_as_uint(l0[o0]);
      al[i][1] = __float_as_uint(l0[o0+8]);
      al[i][2] = __float_as_uint(l1[o0]);
      al[i][3] = __float_as_uint(l1[o0+8]);
    }
    #pragma unroll
    for (int n = 0; n < 4; n++) {
      float x0 = Xp[(kr+tg)*LDW + 8*n + g];
      float x1 = Xp[(kr+tg+4)*LDW + 8*n + g];
      unsigned bh[2], bl[2];
      split3(x0, bh[0], bl[0]);
      split3(x1, bh[1], bl[1]);
      mma8(acc[0][n], al[0], bh);
      mma8(acc[0][n], ah[0], bl);
      mma8(acc[0][n], ah[0], bh);
      mma8(acc[1][n], al[1], bh);
      mma8(acc[1][n], ah[1], bl);
      mma8(acc[1][n], ah[1], bh);
    }
  }
}

// Same with relu(bn(.)) on X before split (gemm2). sa/sd indexed by absolute k.
__device__ __forceinline__ void cmma4_bn(const float* Whp, const float* Wlp, const float* Xp,
                                         const float* sa, const float* sd, int kc,
                                         int g, int tg, float (&acc)[2][4][4]) {
  #pragma unroll
  for (int s = 0; s < 2; s++) {
    int kr = s * 8;
    float A0 = sa[kc+kr+tg],   D0 = sd[kc+kr+tg];
    float A1 = sa[kc+kr+tg+4], D1 = sd[kc+kr+tg+4];
    unsigned ah[2][4], al[2][4];
    const float* h0 = Whp + (kr+tg)*LDW;
    const float* h1 = Whp + (kr+tg+4)*LDW;
    const float* l0 = Wlp + (kr+tg)*LDW;
    const float* l1 = Wlp + (kr+tg+4)*LDW;
    #pragma unroll
    for (int i = 0; i < 2; i++) {
      int o0 = 16*i + g;
      ah[i][0] = __float_as_uint(h0[o0]);
      ah[i][1] = __float_as_uint(h0[o0+8]);
      ah[i][2] = __float_as_uint(h1[o0]);
      ah[i][3] = __float_as_uint(h1[o0+8]);
      al[i][0] = __float_as_uint(l0[o0]);
      al[i][1] = __float_as_uint(l0[o0+8]);
      al[i][2] = __float_as_uint(l1[o0]);
      al[i][3] = __float_as_uint(l1[o0+8]);
    }
    #pragma unroll
    for (int n = 0; n < 4; n++) {
      float x0 = fmaxf(fmaf(A0, Xp[(kr+tg)*LDW + 8*n + g], D0), 0.0f);
      float x1 = fmaxf(fmaf(A1, Xp[(kr+tg+4)*LDW + 8*n + g], D1), 0.0f);
      unsigned bh[2], bl[2];
      split3(x0, bh[0], bl[0]);
      split3(x1, bh[1], bl[1]);
      mma8(acc[0][n], al[0], bh);
      mma8(acc[0][n], ah[0], bl);
      mma8(acc[0][n], ah[0], bh);
      mma8(acc[1][n], al[1], bh);
      mma8(acc[1][n], ah[1], bl);
      mma8(acc[1][n], ah[1], bh);
    }
  }
}

// ---------------- W transpose + hi/lo split ----------------
__global__ __launch_bounds__(256) void split_w_kernel(
    const float* __restrict__ W1, const float* __restrict__ W2) {
  int e = blockIdx.x * 256 + threadIdx.x;   // 65536
  float w; float* hi; float* lo; int idx;
  if (e < 384*128) {
    int k = e >> 7, o = e & 127;
    w = W1[o*384 + k]; hi = d_W1hi; lo = d_W1lo; idx = e;
  } else {
    int e2 = e - 384*128;
    int k = e2 >> 7, o = e2 & 127;
    w = W2[o*128 + k]; hi = d_W2hi; lo = d_W2lo; idx = e2;
  }
  unsigned h, l;
  split3(w, h, l);
  hi[idx] = __uint_as_float(h);
  lo[idx] = __uint_as_float(l);
}

// ---------------- 3-NN: 2 queries/thread, point dim split in 2 ----------------
__global__ __launch_bounds__(256) void knn_kernel(
    const float* __restrict__ xyz, const float* __restrict__ sub_xyz) {
  __shared__ float4 pts[PH];
  int bx = blockIdx.x;                      // 128 blocks
  int b    = bx >> 6;
  int half = (bx >> 5) & 1;
  int m0   = ((bx & 31) << 9) + threadIdx.x;
  const float* sp = sub_xyz + (size_t)b * 3 * Np + half * PH;
  for (int i = threadIdx.x; i < PH; i += 256) {
    float px = sp[i], py = sp[Np + i], pz = sp[2*Np + i];
    pts[i] = make_float4(px, py, pz, fmaf(px, px, fmaf(py, py, pz*pz)));
  }
  __syncthreads();
  const float* qp = xyz + (size_t)b * 3 * Mq;
  int mA = m0, mB = m0 + 256;
  float nxA = -2.f*qp[mA], nyA = -2.f*qp[Mq+mA], nzA = -2.f*qp[2*Mq+mA];
  float nxB = -2.f*qp[mB], nyB = -2.f*qp[Mq+mB], nzB = -2.f*qp[2*Mq+mB];

  float a0=3.4e38f,a1=3.4e38f,a2=3.4e38f; int ja0=0,ja1=0,ja2=0;
  float b0=3.4e38f,b1=3.4e38f,b2=3.4e38f; int jb0=0,jb1=0,jb2=0;
  #pragma unroll 4
  for (int i = 0; i < PH; i++) {
    float4 p = pts[i];
    float eA = fmaf(nxA, p.x, fmaf(nyA, p.y, fmaf(nzA, p.z, p.w)));
    float eB = fmaf(nxB, p.x, fmaf(nyB, p.y, fmaf(nzB, p.z, p.w)));
    if (eA < a2) {
      if (eA < a1) {
        a2 = a1; ja2 = ja1;
        if (eA < a0) { a1 = a0; ja1 = ja0; a0 = eA; ja0 = i; }
        else         { a1 = eA; ja1 = i; }
      } else { a2 = eA; ja2 = i; }
    }
    if (eB < b2) {
      if (eB < b1) {
        b2 = b1; jb2 = jb1;
        if (eB < b0) { b1 = b0; jb1 = jb0; b0 = eB; jb0 = i; }
        else         { b1 = eB; jb1 = i; }
      } else { b2 = eB; jb2 = i; }
    }
  }
  int off = half * PH;
  size_t baseA = ((size_t)(b * Mq + mA) * 2 + half) * 3;
  d_cd[baseA+0]=a0; d_cd[baseA+1]=a1; d_cd[baseA+2]=a2;
  d_ci[baseA+0]=ja0+off; d_ci[baseA+1]=ja1+off; d_ci[baseA+2]=ja2+off;
  size_t baseB = ((size_t)(b * Mq + mB) * 2 + half) * 3;
  d_cd[baseB+0]=b0; d_cd[baseB+1]=b1; d_cd[baseB+2]=b2;
  d_ci[baseB+0]=jb0+off; d_ci[baseB+1]=jb1+off; d_ci[baseB+2]=jb2+off;
}

// ---------------- merge 6 candidates ----------------
__global__ __launch_bounds__(256) void knn_merge_kernel(const float* __restrict__ xyz) {
  int g = blockIdx.x * 256 + threadIdx.x;
  int b = g >> 14, m = g & (Mq - 1);
  const float* qp = xyz + (size_t)b * 3 * Mq;
  float qx = qp[m], qy = qp[Mq + m], qz = qp[2*Mq + m];
  float qq = fmaf(qx, qx, fmaf(qy, qy, qz*qz));
  float c0 = 3.4e38f, c1 = 3.4e38f, c2 = 3.4e38f;
  int j0 = 0, j1 = 0, j2 = 0;
  size_t base = (size_t)g * 6;
  #pragma unroll
  for (int t = 0; t < 6; t++) {
    float e = d_cd[base + t];
    int  id = d_ci[base + t];
    if (e < c2) {
      if (e < c1) {
        c2 = c1; j2 = j1;
        if (e < c0) { c1 = c0; j1 = j0; c0 = e; j0 = id; }
        else        { c1 = e; j1 = id; }
      } else { c2 = e; j2 = id; }
    }
  }
  float d0  = fmaxf(c0 + qq, 0.0f);
  float d1  = fmaxf(c1 + qq, 0.0f);
  float d2v = fmaxf(c2 + qq, 0.0f);
  float w0 = 1.0f / (d0 + 1e-8f);
  float w1 = 1.0f / (d1 + 1e-8f);
  float w2 = 1.0f / (d2v + 1e-8f);
  float inv = 1.0f / (w0 + w1 + w2);
  d_idx[g*3+0]=j0; d_idx[g*3+1]=j1; d_idx[g*3+2]=j2;
  d_w[g*3+0]=w0*inv; d_w[g*3+1]=w1*inv; d_w[g*3+2]=w2*inv;
}

// ---------------- P = W1[:,128:384] @ sub_x; block 128o x 128n, 512 thr, grid 64 ----------------
__global__ __launch_bounds__(512, 1) void gemmP_kernel(const float* __restrict__ sub_x) {
  extern __shared__ float smem[];
  int tid = threadIdx.x;
  int lane = tid & 31, warp = tid >> 5;      // 16 warps
  int g = lane >> 2, tg = lane & 3;
  int ow = (warp & 3) * 32, mw = (warp >> 2) * 32;
  int bx = blockIdx.x;
  int b = bx >> 5, n0 = (bx & 31) << 7;
  const float* xb = sub_x + (size_t)b * CsF * Np;

  float acc[2][4][4];
  #pragma unroll
  for (int i = 0; i < 2; i++)
    #pragma unroll
    for (int n = 0; n < 4; n++)
      #pragma unroll
      for (int r = 0; r < 4; r++) acc[i][n][r] = 0.0f;

  int kkL = tid >> 5, cL = (tid & 31) << 2;
  auto load_chunk = [&](int kc, int s) {
    float* st = smem + s*STG;
    size_t go = (size_t)(Cin + kc + kkL)*128 + cL;
    cp16(st + kkL*LDW + cL,        d_W1hi + go);
    cp16(st + 2176 + kkL*LDW + cL, d_W1lo + go);
    cp16(st + 4352 + kkL*LDW + cL, xb + (size_t)(kc + kkL)*Np + n0 + cL);
  };
  load_chunk(0, 0); cp_commit();
  for (int ch = 0; ch < 16; ch++) {
    if (ch < 15) { load_chunk((ch+1)*16, (ch+1)&1); cp_commit(); cp_wait<1>(); }
    else         { cp_wait<0>(); }
    __syncthreads();
    const float* st = smem + (ch&1)*STG;
    cmma4(st + ow, st + 2176 + ow, st + 4352 + mw, g, tg, acc);
    __syncthreads();
  }

  // stage Z[o][n] stride LDW, then store P[n][o]
  float* Zs = smem;
  #pragma unroll
  for (int i = 0; i < 2; i++)
    #pragma unroll
    for (int n = 0; n < 4; n++) {
      int o = ow + 16*i + g;
      int m = mw + 8*n + 2*tg;
      *(float2*)&Zs[(size_t)o*LDW + m]     = make_float2(acc[i][n][0], acc[i][n][1]);
      *(float2*)&Zs[(size_t)(o+8)*LDW + m] = make_float2(acc[i][n][2], acc[i][n][3]);
    }
  __syncthreads();
  int nl = tid & 127, oh = tid >> 7;   // 4 o-quarters of 32
  float* dst = d_P + ((size_t)b * Np + n0 + nl) * 128;
  #pragma unroll
  for (int o = oh*32; o < oh*32 + 32; o += 4) {
    float4 v = make_float4(Zs[(o+0)*LDW + nl], Zs[(o+1)*LDW + nl],
                           Zs[(o+2)*LDW + nl], Zs[(o+3)*LDW + nl]);
    *(float4*)(dst + o) = v;
  }
}

// ---------------- z1 = W1a @ x + gather(P); block 128o x 128m, 512 thr, grid 256 ----------------
__global__ __launch_bounds__(512, 1) void gemm1_kernel(const float* __restrict__ x) {
  extern __shared__ float smem[];
  int*   sidx = (int*)(smem + 17408);     // 384
  float* sw   = smem + 17408 + 384;       // 384
  int tid = threadIdx.x;
  int lane = tid & 31, warp = tid >> 5;
  int g = lane >> 2, tg = lane & 3;
  int ow = (warp & 3) * 32, mw = (warp >> 2) * 32;
  int bx = blockIdx.x;
  int b = bx >> 7, m0 = (bx & 127) << 7;
  const float* xb = x + (size_t)b * Cin * Mq;

  if (tid < 384) {
    size_t cb = ((size_t)(b * Mq + m0)) * 3 + tid;
    sidx[tid] = d_idx[cb]; sw[tid] = d_w[cb];
  }

  float acc[2][4][4];
  #pragma unroll
  for (int i = 0; i < 2; i++)
    #pragma unroll
    for (int n = 0; n < 4; n++)
      #pragma unroll
      for (int r = 0; r < 4; r++) acc[i][n][r] = 0.0f;

  int kkL = tid >> 5, cL = (tid & 31) << 2;
  auto load_chunk = [&](int kc, int s) {
    float* st = smem + s*STG;
    size_t go = (size_t)(kc + kkL)*128 + cL;
    cp16(st + kkL*LDW + cL,        d_W1hi + go);
    cp16(st + 2176 + kkL*LDW + cL, d_W1lo + go);
    cp16(st + 4352 + kkL*LDW + cL, xb + (size_t)(kc + kkL)*Mq + m0 + cL);
  };
  load_chunk(0, 0); cp_commit();
  for (int ch = 0; ch < 8; ch++) {
    if (ch < 7) { load_chunk((ch+1)*16, (ch+1)&1); cp_commit(); cp_wait<1>(); }
    else        { cp_wait<0>(); }
    __syncthreads();
    const float* st = smem + (ch&1)*STG;
    cmma4(st + ow, st + 2176 + ow, st + 4352 + mw, g, tg, acc);
    __syncthreads();
  }

  // acc -> Zs[o][m] (128x136)
  float* Zs = smem;
  #pragma unroll
  for (int i = 0; i < 2; i++)
    #pragma unroll
    for (int n = 0; n < 4; n++) {
      int o = ow + 16*i + g;
      int m = mw + 8*n + 2*tg;
      *(float2*)&Zs[(size_t)o*LDW + m]     = make_float2(acc[i][n][0], acc[i][n][1]);
      *(float2*)&Zs[(size_t)(o+8)*LDW + m] = make_float2(acc[i][n][2], acc[i][n][3]);
    }
  __syncthreads();

  // gather-interpolate + store z1 + write back for stats
  int mcol = tid & 127, oq = tid >> 7;    // 4 o-quarters of 32
  int i0 = sidx[mcol*3+0], i1 = sidx[mcol*3+1], i2 = sidx[mcol*3+2];
  float w0 = sw[mcol*3+0], w1 = sw[mcol*3+1], w2 = sw[mcol*3+2];
  const float* P0 = d_P + ((size_t)b*Np + i0) * 128;
  const float* P1 = d_P + ((size_t)b*Np + i1) * 128;
  const float* P2 = d_P + ((size_t)b*Np + i2) * 128;
  float* zb = d_z1 + (size_t)b * DoC * Mq + m0 + mcol;
  #pragma unroll 2
  for (int o = oq*32; o < oq*32 + 32; o += 4) {
    float4 q0 = *(const float4*)(P0 + o);
    float4 q1 = *(const float4*)(P1 + o);
    float4 q2 = *(const float4*)(P2 + o);
    float v0 = Zs[(o+0)*LDW + mcol] + w0*q0.x + w1*q1.x + w2*q2.x;
    float v1 = Zs[(o+1)*LDW + mcol] + w0*q0.y + w1*q1.y + w2*q2.y;
    float v2 = Zs[(o+2)*LDW + mcol] + w0*q0.z + w1*q1.z + w2*q2.z;
    float v3 = Zs[(o+3)*LDW + mcol] + w0*q0.w + w1*q1.w + w2*q2.w;
    zb[(size_t)(o+0)*Mq] = v0;
    zb[(size_t)(o+1)*Mq] = v1;
    zb[(size_t)(o+2)*Mq] = v2;
    zb[(size_t)(o+3)*Mq] = v3;
    Zs[(o+0)*LDW + mcol] = v0;
    Zs[(o+1)*LDW + mcol] = v1;
    Zs[(o+2)*LDW + mcol] = v2;
    Zs[(o+3)*LDW + mcol] = v3;
  }
  __syncthreads();
  if (tid < 128) {
    const float* zr = &Zs[(size_t)tid * LDW];
    float s = 0.0f, q = 0.0f;
    #pragma unroll 8
    for (int m = 0; m < 128; m += 4) {
      float4 v = *(const float4*)(zr + m);
      s += v.x + v.y + v.z + v.w;
      q += v.x*v.x + v.y*v.y + v.z*v.z + v.w*v.w;
    }
    d_psum[bx * DoC + tid] = s;
    d_psq [bx * DoC + tid] = q;
  }
}

// ---------------- BN finalize ----------------
__global__ void bn_finalize_kernel(const float* __restrict__ g,
                                   const float* __restrict__ bias, int which) {
  __shared__ float ss[512], sq[512];
  int tid = threadIdx.x;
  int ch = tid & 127, part = tid >> 7;
  float s = 0.0f, q = 0.0f;
  for (int blk = part; blk < NBLK; blk += 4) {
    s += d_psum[blk * DoC + ch];
    q += d_psq [blk * DoC + ch];
  }
  ss[tid] = s; sq[tid] = q;
  __syncthreads();
  if (tid < 128) {
    float S = ss[tid] + ss[tid+128] + ss[tid+256] + ss[tid+384];
    float Q = sq[tid] + sq[tid+128] + sq[tid+256] + sq[tid+384];
    const float invN = 1.0f / (float)NCOLS;
    float mean = S * invN;
    float var  = Q * invN - mean * mean;
    float rstd = rsqrtf(var + 1e-5f);
    float a = g[tid] * rstd;
    float d = bias[tid] - mean * a;
    float* ab = which ? d_bn2 : d_bn1;
    ab[tid] = a; ab[DoC + tid] = d;
  }
}

// ---------------- z2 = W2 @ relu(bn1(z1)); block 128o x 128m, 512 thr, grid 256 ----------------
__global__ __launch_bounds__(512, 1) void gemm2_kernel() {
  extern __shared__ float smem[];
  float* sa = smem + 17408;        // 128
  float* sd = smem + 17408 + 128;  // 128
  int tid = threadIdx.x;
  int lane = tid & 31, warp = tid >> 5;
  int g = lane >> 2, tg = lane & 3;
  int ow = (warp & 3) * 32, mw = (warp >> 2) * 32;
  int bx = blockIdx.x;
  int b = bx >> 7, m0 = (bx & 127) << 7;
  if (tid < 128) { sa[tid] = d_bn1[tid]; sd[tid] = d_bn1[DoC + tid]; }
  const float* zb0 = d_z1 + (size_t)b * DoC * Mq;

  float acc[2][4][4];
  #pragma unroll
  for (int i = 0; i < 2; i++)
    #pragma unroll
    for (int n = 0; n < 4; n++)
      #pragma unroll
      for (int r = 0; r < 4; r++) acc[i][n][r] = 0.0f;

  int kkL = tid >> 5, cL = (tid & 31) << 2;
  auto load_chunk = [&](int kc, int s) {
    float* st = smem + s*STG;
    size_t go = (size_t)(kc + kkL)*128 + cL;
    cp16(st + kkL*LDW + cL,        d_W2hi + go);
    cp16(st + 2176 + kkL*LDW + cL, d_W2lo + go);
    cp16(st + 4352 + kkL*LDW + cL, zb0 + (size_t)(kc + kkL)*Mq + m0 + cL);
  };
  load_chunk(0, 0); cp_commit();
  __syncthreads();   // sa/sd visible before first cmma4_bn
  for (int ch = 0; ch < 8; ch++) {
    if (ch < 7) { load_chunk((ch+1)*16, (ch+1)&1); cp_commit(); cp_wait<1>(); }
    else        { cp_wait<0>(); }
    __syncthreads();
    const float* st = smem + (ch&1)*STG;
    cmma4_bn(st + ow, st + 2176 + ow, st + 4352 + mw, sa, sd, ch*16, g, tg, acc);
    __syncthreads();
  }

  float* Zs = smem;
  #pragma unroll
  for (int i = 0; i < 2; i++)
    #pragma unroll
    for (int n = 0; n < 4; n++) {
      int o = ow + 16*i + g;
      int m = mw + 8*n + 2*tg;
      *(float2*)&Zs[(size_t)o*LDW + m]     = make_float2(acc[i][n][0], acc[i][n][1]);
      *(float2*)&Zs[(size_t)(o+8)*LDW + m] = make_float2(acc[i][n][2], acc[i][n][3]);
    }
  __syncthreads();

  int mcol = tid & 127, oq = tid >> 7;
  float* zb = d_z2 + (size_t)b * DoC * Mq + m0 + mcol;
  #pragma unroll 2
  for (int o = oq*32; o < oq*32 + 32; o += 4) {
    zb[(size_t)(o+0)*Mq] = Zs[(o+0)*LDW + mcol];
    zb[(size_t)(o+1)*Mq] = Zs[(o+1)*LDW + mcol];
    zb[(size_t)(o+2)*Mq] = Zs[(o+2)*LDW + mcol];
    zb[(size_t)(o+3)*Mq] = Zs[(o+3)*LDW + mcol];
  }
  __syncthreads();
  if (tid < 128) {
    const float* zr = &Zs[(size_t)tid * LDW];
    float s = 0.0f, q = 0.0f;
    #pragma unroll 8
    for (int m = 0; m < 128; m += 4) {
      float4 v = *(const float4*)(zr + m);
      s += v.x + v.y + v.z + v.w;
      q += v.x*v.x + v.y*v.y + v.z*v.z + v.w*v.w;
    }
    d_psum[bx * DoC + tid] = s;
    d_psq [bx * DoC + tid] = q;
  }
}

// ---------------- out = relu(bn2(z2)) ----------------
__global__ __launch_bounds__(256) void final_kernel(float* __restrict__ out) {
  int e4 = blockIdx.x * 256 + threadIdx.x;
  int ch = (e4 >> 12) & 127;
  float a = d_bn2[ch], d = d_bn2[DoC + ch];
  float4 v = *((const float4*)d_z2 + e4);
  v.x = fmaxf(fmaf(a, v.x, d), 0.0f);
  v.y = fmaxf(fmaf(a, v.y, d), 0.0f);
  v.z = fmaxf(fmaf(a, v.z, d), 0.0f);
  v.w = fmaxf(fmaf(a, v.w, d), 0.0f);
  *((float4*)out + e4) = v;
}

// ---------------- launch ----------------
extern "C" void kernel_launch(void* const* d_in, const int* in_sizes, int n_in,
                              void* d_out, int out_size) {
  const float* x       = (const float*)d_in[0];
  const float* xyz     = (const float*)d_in[1];
  const float* sub_x   = (const float*)d_in[2];
  const float* sub_xyz = (const float*)d_in[3];
  const float* W1      = (const float*)d_in[4];
  const float* g1      = (const float*)d_in[5];
  const float* b1      = (const float*)d_in[6];
  const float* W2      = (const float*)d_in[7];
  const float* g2      = (const float*)d_in[8];
  const float* b2      = (const float*)d_in[9];
  float* out = (float*)d_out;

  // dynamic smem: stages 2*STG floats; epilogue Zs 128*136 = 17408 floats (aliased)
  const int smemP  = 17408 * 4;                 // 69632 B
  const int smem1  = (17408 + 768) * 4;         // 72704 B
  const int smem2  = (17408 + 256) * 4;         // 70656 B
  cudaFuncSetAttribute(gemmP_kernel, cudaFuncAttributeMaxDynamicSharedMemorySize, smemP);
  cudaFuncSetAttribute(gemm1_kernel, cudaFuncAttributeMaxDynamicSharedMemorySize, smem1);
  cudaFuncSetAttribute(gemm2_kernel, cudaFuncAttributeMaxDynamicSharedMemorySize, smem2);

  split_w_kernel<<<256, 256>>>(W1, W2);
  knn_kernel<<<128, 256>>>(xyz, sub_xyz);
  knn_merge_kernel<<<128, 256>>>(xyz);
  gemmP_kernel<<<64, 512, smemP>>>(sub_x);
  gemm1_kernel<<<256, 512, smem1>>>(x);
  bn_finalize_kernel<<<1, 512>>>(g1, b1, 0);
  gemm2_kernel<<<256, 512, smem2>>>();
  bn_finalize_kernel<<<1, 512>>>(g2, b2, 1);
  final_kernel<<<4096, 256>>>(out);
}

// round 8
// speedup vs baseline: 1.1391x; 1.1302x over previous
#include <cuda_runtime.h>

#define Bc   2
#define Mq   16384
#define Np   4096
#define Cin  128
#define CsF  256
#define DoC  128
#define NCOLS (Bc*Mq)
#define NBLK  256            // gemm1/gemm2 grid (stats blocks)
#define PH   1024            // knn points per quarter

// ---------------- scratch (device globals) ----------------
__device__ __align__(16) float d_W1t[384*128];   // k-major
__device__ __align__(16) float d_W2t[128*128];
__device__ __align__(16) float d_P  [Bc*Np*DoC];
__device__ float d_cd[Bc*Mq*12];
__device__ int   d_ci[Bc*Mq*12];
__device__ int   d_idx[Bc*Mq*3];
__device__ float d_w  [Bc*Mq*3];
__device__ __align__(16) float d_z1 [Bc*DoC*Mq];
__device__ __align__(16) float d_z2 [Bc*DoC*Mq];
__device__ float d_psum[NBLK*DoC];
__device__ float d_psq [NBLK*DoC];
__device__ float d_bn1[2*DoC];
__device__ float d_bn2[2*DoC];

// ---------------- helpers ----------------
__device__ __forceinline__ void cp16(float* s, const float* g) {
  unsigned sa = (unsigned)__cvta_generic_to_shared(s);
  asm volatile("cp.async.cg.shared.global [%0], [%1], 16;\n" :: "r"(sa), "l"(g));
}
__device__ __forceinline__ void cp_commit() { asm volatile("cp.async.commit_group;\n"); }
template<int N> __device__ __forceinline__ void cp_wait() {
  asm volatile("cp.async.wait_group %0;\n" :: "n"(N));
}

// ---------------- W transpose ----------------
__global__ __launch_bounds__(256) void transpose_w_kernel(
    const float* __restrict__ W1, const float* __restrict__ W2) {
  int e = blockIdx.x * 256 + threadIdx.x;   // 65536
  if (e < 384*128) {
    int k = e >> 7, o = e & 127;
    d_W1t[e] = W1[o*384 + k];
  } else {
    int e2 = e - 384*128;
    int k = e2 >> 7, o = e2 & 127;
    d_W2t[e2] = W2[o*128 + k];
  }
}

// ---------------- 3-NN: 2 queries/thread, point dim split in 4 ----------------
__global__ __launch_bounds__(256) void knn_kernel(
    const float* __restrict__ xyz, const float* __restrict__ sub_xyz) {
  __shared__ float4 pts[PH];   // 16KB
  int bx = blockIdx.x;                      // 256 blocks
  int b    = bx >> 7;                       // 2
  int half = (bx >> 5) & 3;                 // 4
  int m0   = ((bx & 31) << 9) + threadIdx.x;
  const float* sp = sub_xyz + (size_t)b * 3 * Np + half * PH;
  for (int i = threadIdx.x; i < PH; i += 256) {
    float px = sp[i], py = sp[Np + i], pz = sp[2*Np + i];
    pts[i] = make_float4(px, py, pz, fmaf(px, px, fmaf(py, py, pz*pz)));
  }
  __syncthreads();
  const float* qp = xyz + (size_t)b * 3 * Mq;
  int mA = m0, mB = m0 + 256;
  float nxA = -2.f*qp[mA], nyA = -2.f*qp[Mq+mA], nzA = -2.f*qp[2*Mq+mA];
  float nxB = -2.f*qp[mB], nyB = -2.f*qp[Mq+mB], nzB = -2.f*qp[2*Mq+mB];

  float a0=3.4e38f,a1=3.4e38f,a2=3.4e38f; int ja0=0,ja1=0,ja2=0;
  float b0=3.4e38f,b1=3.4e38f,b2=3.4e38f; int jb0=0,jb1=0,jb2=0;
  #pragma unroll 4
  for (int i = 0; i < PH; i++) {
    float4 p = pts[i];
    float eA = fmaf(nxA, p.x, fmaf(nyA, p.y, fmaf(nzA, p.z, p.w)));
    float eB = fmaf(nxB, p.x, fmaf(nyB, p.y, fmaf(nzB, p.z, p.w)));
    if (eA < a2) {
      if (eA < a1) {
        a2 = a1; ja2 = ja1;
        if (eA < a0) { a1 = a0; ja1 = ja0; a0 = eA; ja0 = i; }
        else         { a1 = eA; ja1 = i; }
      } else { a2 = eA; ja2 = i; }
    }
    if (eB < b2) {
      if (eB < b1) {
        b2 = b1; jb2 = jb1;
        if (eB < b0) { b1 = b0; jb1 = jb0; b0 = eB; jb0 = i; }
        else         { b1 = eB; jb1 = i; }
      } else { b2 = eB; jb2 = i; }
    }
  }
  int off = half * PH;
  size_t baseA = ((size_t)(b * Mq + mA) * 4 + half) * 3;
  d_cd[baseA+0]=a0; d_cd[baseA+1]=a1; d_cd[baseA+2]=a2;
  d_ci[baseA+0]=ja0+off; d_ci[baseA+1]=ja1+off; d_ci[baseA+2]=ja2+off;
  size_t baseB = ((size_t)(b * Mq + mB) * 4 + half) * 3;
  d_cd[baseB+0]=b0; d_cd[baseB+1]=b1; d_cd[baseB+2]=b2;
  d_ci[baseB+0]=jb0+off; d_ci[baseB+1]=jb1+off; d_ci[baseB+2]=jb2+off;
}

// ---------------- merge 12 candidates ----------------
__global__ __launch_bounds__(256) void knn_merge_kernel(const float* __restrict__ xyz) {
  int g = blockIdx.x * 256 + threadIdx.x;   // 0..32767
  int b = g >> 14, m = g & (Mq - 1);
  const float* qp = xyz + (size_t)b * 3 * Mq;
  float qx = qp[m], qy = qp[Mq + m], qz = qp[2*Mq + m];
  float qq = fmaf(qx, qx, fmaf(qy, qy, qz*qz));
  float c0 = 3.4e38f, c1 = 3.4e38f, c2 = 3.4e38f;
  int j0 = 0, j1 = 0, j2 = 0;
  size_t base = (size_t)g * 12;
  #pragma unroll
  for (int t = 0; t < 12; t++) {            // half order ascending -> stable ties
    float e = d_cd[base + t];
    int  id = d_ci[base + t];
    if (e < c2) {
      if (e < c1) {
        c2 = c1; j2 = j1;
        if (e < c0) { c1 = c0; j1 = j0; c0 = e; j0 = id; }
        else        { c1 = e; j1 = id; }
      } else { c2 = e; j2 = id; }
    }
  }
  float d0  = fmaxf(c0 + qq, 0.0f);
  float d1  = fmaxf(c1 + qq, 0.0f);
  float d2v = fmaxf(c2 + qq, 0.0f);
  float w0 = 1.0f / (d0 + 1e-8f);
  float w1 = 1.0f / (d1 + 1e-8f);
  float w2 = 1.0f / (d2v + 1e-8f);
  float inv = 1.0f / (w0 + w1 + w2);
  d_idx[g*3+0]=j0; d_idx[g*3+1]=j1; d_idx[g*3+2]=j2;
  d_w[g*3+0]=w0*inv; d_w[g*3+1]=w1*inv; d_w[g*3+2]=w2*inv;
}

// ---------------- P = W1[:,128:384] @ sub_x; tile 64o x 128n, grid 128 ----------------
__global__ __launch_bounds__(256, 2) void gemmP_kernel(const float* __restrict__ sub_x) {
  __shared__ float Ws[2][16][64];
  __shared__ float Xs[2][16][128];
  int tid = threadIdx.x;
  int tx = tid & 15, ty = tid >> 4;
  int bx = blockIdx.x;
  int b  = bx >> 6, ot = (bx >> 5) & 1, nt = bx & 31;
  int o0 = ot * 64, n0 = nt * 128;
  const float* xb = sub_x + (size_t)b * CsF * Np;

  float acc[4][8];
  #pragma unroll
  for (int i = 0; i < 4; i++)
    #pragma unroll
    for (int j = 0; j < 8; j++) acc[i][j] = 0.0f;

  auto load_chunk = [&](int kc, int s) {
    {  // W: 16x64 = 1024 floats, 1 cp16/thread
      int kk = tid >> 4, c = (tid & 15) << 2;
      cp16(&Ws[s][kk][c], d_W1t + (size_t)(Cin + kc + kk)*128 + o0 + c);
    }
    #pragma unroll
    for (int k = 0; k < 2; k++) {  // X: 16x128 = 2048 floats
      int e4 = tid + k*256, kk = e4 >> 5, c = (e4 & 31) << 2;
      cp16(&Xs[s][kk][c], xb + (size_t)(kc + kk)*Np + n0 + c);
    }
  };
  load_chunk(0, 0); cp_commit();
  for (int ch = 0; ch < 16; ch++) {
    if (ch < 15) { load_chunk((ch+1)*16, (ch+1)&1); cp_commit(); cp_wait<1>(); }
    else         { cp_wait<0>(); }
    __syncthreads();
    int s = ch & 1;
    #pragma unroll
    for (int kk = 0; kk < 16; kk++) {
      float a[4], bb[8];
      *(float4*)&a[0]  = *(const float4*)&Ws[s][kk][ty*4];
      *(float4*)&bb[0] = *(const float4*)&Xs[s][kk][tx*8];
      *(float4*)&bb[4] = *(const float4*)&Xs[s][kk][tx*8+4];
      #pragma unroll
      for (int i = 0; i < 4; i++)
        #pragma unroll
        for (int j = 0; j < 8; j++) acc[i][j] = fmaf(a[i], bb[j], acc[i][j]);
    }
    __syncthreads();
  }
  // store P[n][o]: per thread 8 n-rows, 4 consecutive o
  #pragma unroll
  for (int j = 0; j < 8; j++) {
    float* dst = &d_P[(((size_t)b * Np) + n0 + tx*8 + j) * 128 + o0 + ty*4];
    *(float4*)dst = make_float4(acc[0][j], acc[1][j], acc[2][j], acc[3][j]);
  }
}

// ---------------- z1 = W1a @ x + gather(P), + shfl stats; tile 128x128, grid 256 ----------------
__global__ __launch_bounds__(256, 2) void gemm1_kernel(const float* __restrict__ x) {
  __shared__ float Ws[2][16][128];
  __shared__ float Xs[2][16][128];
  __shared__ int   sidx[384];
  __shared__ float sw[384];
  int tid = threadIdx.x;
  int tx = tid & 15, ty = tid >> 4;
  int bx = blockIdx.x;
  int b = bx >> 7, m0 = (bx & 127) << 7;
  const float* xb = x + (size_t)b * Cin * Mq;

  {
    size_t cb = ((size_t)(b * Mq + m0)) * 3;
    for (int e = tid; e < 384; e += 256) { sidx[e] = d_idx[cb + e]; sw[e] = d_w[cb + e]; }
  }

  float acc[8][8];
  #pragma unroll
  for (int i = 0; i < 8; i++)
    #pragma unroll
    for (int j = 0; j < 8; j++) acc[i][j] = 0.0f;

  auto load_chunk = [&](int kc, int s) {
    #pragma unroll
    for (int k = 0; k < 2; k++) {
      int e4 = tid + k*256, kk = e4 >> 5, c = (e4 & 31) << 2;
      cp16(&Ws[s][kk][c], d_W1t + (size_t)(kc + kk)*128 + c);
      cp16(&Xs[s][kk][c], xb + (size_t)(kc + kk)*Mq + m0 + c);
    }
  };
  load_chunk(0, 0); cp_commit();
  for (int ch = 0; ch < 8; ch++) {
    if (ch < 7) { load_chunk((ch+1)*16, (ch+1)&1); cp_commit(); cp_wait<1>(); }
    else        { cp_wait<0>(); }
    __syncthreads();
    int s = ch & 1;
    #pragma unroll
    for (int kk = 0; kk < 16; kk++) {
      float a[8], bb[8];
      *(float4*)&a[0]  = *(const float4*)&Ws[s][kk][ty*8];
      *(float4*)&a[4]  = *(const float4*)&Ws[s][kk][ty*8+4];
      *(float4*)&bb[0] = *(const float4*)&Xs[s][kk][tx*8];
      *(float4*)&bb[4] = *(const float4*)&Xs[s][kk][tx*8+4];
      #pragma unroll
      for (int i = 0; i < 8; i++)
        #pragma unroll
        for (int j = 0; j < 8; j++) acc[i][j] = fmaf(a[i], bb[j], acc[i][j]);
    }
    __syncthreads();
  }

  // gather-interpolate through P
  #pragma unroll
  for (int j = 0; j < 8; j++) {
    int col = tx*8 + j;
    #pragma unroll
    for (int t = 0; t < 3; t++) {
      int   id = sidx[col*3 + t];
      float wt = sw  [col*3 + t];
      const float* pr = &d_P[(((size_t)b * Np) + id) * 128 + ty*8];
      float4 p0 = *(const float4*)pr;
      float4 p1 = *(const float4*)(pr + 4);
      acc[0][j] = fmaf(wt, p0.x, acc[0][j]);
      acc[1][j] = fmaf(wt, p0.y, acc[1][j]);
      acc[2][j] = fmaf(wt, p0.z, acc[2][j]);
      acc[3][j] = fmaf(wt, p0.w, acc[3][j]);
      acc[4][j] = fmaf(wt, p1.x, acc[4][j]);
      acc[5][j] = fmaf(wt, p1.y, acc[5][j]);
      acc[6][j] = fmaf(wt, p1.z, acc[6][j]);
      acc[7][j] = fmaf(wt, p1.w, acc[7][j]);
    }
  }

  // store z1
  #pragma unroll
  for (int i = 0; i < 8; i++) {
    float* dst = &d_z1[((size_t)(b * DoC + ty*8 + i)) * Mq + m0 + tx*8];
    *(float4*)dst       = make_float4(acc[i][0], acc[i][1], acc[i][2], acc[i][3]);
    *(float4*)(dst + 4) = make_float4(acc[i][4], acc[i][5], acc[i][6], acc[i][7]);
  }

  // shfl-butterfly stats over the 16 tx lanes of each half-warp
  float s8[8], q8[8];
  #pragma unroll
  for (int i = 0; i < 8; i++) {
    float s = 0.0f, q = 0.0f;
    #pragma unroll
    for (int j = 0; j < 8; j++) { s += acc[i][j]; q += acc[i][j]*acc[i][j]; }
    s8[i] = s; q8[i] = q;
  }
  #pragma unroll
  for (int off = 8; off >= 1; off >>= 1) {
    #pragma unroll
    for (int i = 0; i < 8; i++) {
      s8[i] += __shfl_xor_sync(0xffffffffu, s8[i], off);
      q8[i] += __shfl_xor_sync(0xffffffffu, q8[i], off);
    }
  }
  if (tx == 0) {
    #pragma unroll
    for (int i = 0; i < 8; i++) {
      d_psum[bx * DoC + ty*8 + i] = s8[i];
      d_psq [bx * DoC + ty*8 + i] = q8[i];
    }
  }
}

// ---------------- BN finalize ----------------
__global__ void bn_finalize_kernel(const float* __restrict__ g,
                                   const float* __restrict__ bias, int which) {
  __shared__ float ss[512], sq[512];
  int tid = threadIdx.x;
  int ch = tid & 127, part = tid >> 7;
  float s = 0.0f, q = 0.0f;
  for (int blk = part; blk < NBLK; blk += 4) {
    s += d_psum[blk * DoC + ch];
    q += d_psq [blk * DoC + ch];
  }
  ss[tid] = s; sq[tid] = q;
  __syncthreads();
  if (tid < 128) {
    float S = ss[tid] + ss[tid+128] + ss[tid+256] + ss[tid+384];
    float Q = sq[tid] + sq[tid+128] + sq[tid+256] + sq[tid+384];
    const float invN = 1.0f / (float)NCOLS;
    float mean = S * invN;
    float var  = Q * invN - mean * mean;
    float rstd = rsqrtf(var + 1e-5f);
    float a = g[tid] * rstd;
    float d = bias[tid] - mean * a;
    float* ab = which ? d_bn2 : d_bn1;
    ab[tid] = a; ab[DoC + tid] = d;
  }
}

// ---------------- z2 = W2 @ relu(bn1(z1)), + shfl stats; tile 128x128, grid 256 ----------------
__global__ __launch_bounds__(256, 2) void gemm2_kernel() {
  __shared__ float Ws[2][16][128];
  __shared__ float Xs[2][16][128];
  __shared__ float sa[128], sd[128];
  int tid = threadIdx.x;
  int tx = tid & 15, ty = tid >> 4;
  int bx = blockIdx.x;
  int b = bx >> 7, m0 = (bx & 127) << 7;
  if (tid < 128) { sa[tid] = d_bn1[tid]; sd[tid] = d_bn1[DoC + tid]; }
  const float* zb0 = d_z1 + (size_t)b * DoC * Mq;

  float acc[8][8];
  #pragma unroll
  for (int i = 0; i < 8; i++)
    #pragma unroll
    for (int j = 0; j < 8; j++) acc[i][j] = 0.0f;

  auto load_chunk = [&](int kc, int s) {
    #pragma unroll
    for (int k = 0; k < 2; k++) {
      int e4 = tid + k*256, kk = e4 >> 5, c = (e4 & 31) << 2;
      cp16(&Ws[s][kk][c], d_W2t + (size_t)(kc + kk)*128 + c);
      cp16(&Xs[s][kk][c], zb0 + (size_t)(kc + kk)*Mq + m0 + c);
    }
  };
  load_chunk(0, 0); cp_commit();
  for (int ch = 0; ch < 8; ch++) {
    if (ch < 7) { load_chunk((ch+1)*16, (ch+1)&1); cp_commit(); cp_wait<1>(); }
    else        { cp_wait<0>(); }
    __syncthreads();
    int s = ch & 1;
    int kc = ch * 16;
    // relu(bn1(.)) in place on this chunk
    #pragma unroll
    for (int k = 0; k < 2; k++) {
      int e4 = tid + k*256, kk = e4 >> 5, c = (e4 & 31) << 2;
      float A = sa[kc + kk], D = sd[kc + kk];
      float4 v = *(float4*)&Xs[s][kk][c];
      v.x = fmaxf(fmaf(A, v.x, D), 0.0f);
      v.y = fmaxf(fmaf(A, v.y, D), 0.0f);
      v.z = fmaxf(fmaf(A, v.z, D), 0.0f);
      v.w = fmaxf(fmaf(A, v.w, D), 0.0f);
      *(float4*)&Xs[s][kk][c] = v;
    }
    __syncthreads();
    #pragma unroll
    for (int kk = 0; kk < 16; kk++) {
      float a[8], bb[8];
      *(float4*)&a[0]  = *(const float4*)&Ws[s][kk][ty*8];
      *(float4*)&a[4]  = *(const float4*)&Ws[s][kk][ty*8+4];
      *(float4*)&bb[0] = *(const float4*)&Xs[s][kk][tx*8];
      *(float4*)&bb[4] = *(const float4*)&Xs[s][kk][tx*8+4];
      #pragma unroll
      for (int i = 0; i < 8; i++)
        #pragma unroll
        for (int j = 0; j < 8; j++) acc[i][j] = fmaf(a[i], bb[j], acc[i][j]);
    }
    __syncthreads();
  }

  #pragma unroll
  for (int i = 0; i < 8; i++) {
    float* dst = &d_z2[((size_t)(b * DoC + ty*8 + i)) * Mq + m0 + tx*8];
    *(float4*)dst       = make_float4(acc[i][0], acc[i][1], acc[i][2], acc[i][3]);
    *(float4*)(dst + 4) = make_float4(acc[i][4], acc[i][5], acc[i][6], acc[i][7]);
  }

  float s8[8], q8[8];
  #pragma unroll
  for (int i = 0; i < 8; i++) {
    float s = 0.0f, q = 0.0f;
    #pragma unroll
    for (int j = 0; j < 8; j++) { s += acc[i][j]; q += acc[i][j]*acc[i][j]; }
    s8[i] = s; q8[i] = q;
  }
  #pragma unroll
  for (int off = 8; off >= 1; off >>= 1) {
    #pragma unroll
    for (int i = 0; i < 8; i++) {
      s8[i] += __shfl_xor_sync(0xffffffffu, s8[i], off);
      q8[i] += __shfl_xor_sync(0xffffffffu, q8[i], off);
    }
  }
  if (tx == 0) {
    #pragma unroll
    for (int i = 0; i < 8; i++) {
      d_psum[bx * DoC + ty*8 + i] = s8[i];
      d_psq [bx * DoC + ty*8 + i] = q8[i];
    }
  }
}

// ---------------- out = relu(bn2(z2)) ----------------
__global__ __launch_bounds__(256) void final_kernel(float* __restrict__ out) {
  int e4 = blockIdx.x * 256 + threadIdx.x;
  int ch = (e4 >> 12) & 127;
  float a = d_bn2[ch], d = d_bn2[DoC + ch];
  float4 v = *((const float4*)d_z2 + e4);
  v.x = fmaxf(fmaf(a, v.x, d), 0.0f);
  v.y = fmaxf(fmaf(a, v.y, d), 0.0f);
  v.z = fmaxf(fmaf(a, v.z, d), 0.0f);
  v.w = fmaxf(fmaf(a, v.w, d), 0.0f);
  *((float4*)out + e4) = v;
}

// ---------------- launch ----------------
extern "C" void kernel_launch(void* const* d_in, const int* in_sizes, int n_in,
                              void* d_out, int out_size) {
  const float* x       = (const float*)d_in[0];
  const float* xyz     = (const float*)d_in[1];
  const float* sub_x   = (const float*)d_in[2];
  const float* sub_xyz = (const float*)d_in[3];
  const float* W1      = (const float*)d_in[4];
  const float* g1      = (const float*)d_in[5];
  const float* b1      = (const float*)d_in[6];
  const float* W2      = (const float*)d_in[7];
  const float* g2      = (const float*)d_in[8];
  const float* b2      = (const float*)d_in[9];
  float* out = (float*)d_out;

  transpose_w_kernel<<<256, 256>>>(W1, W2);
  knn_kernel<<<256, 256>>>(xyz, sub_xyz);
  knn_merge_kernel<<<128, 256>>>(xyz);
  gemmP_kernel<<<128, 256>>>(sub_x);
  gemm1_kernel<<<256, 256>>>(x);
  bn_finalize_kernel<<<1, 512>>>(g1, b1, 0);
  gemm2_kernel<<<256, 256>>>();
  bn_finalize_kernel<<<1, 512>>>(g2, b2, 1);
  final_kernel<<<4096, 256>>>(out);
}

// round 9
// speedup vs baseline: 1.2424x; 1.0908x over previous
#include <cuda_runtime.h>

#define Bc   2
#define Mq   16384
#define Np   4096
#define Cin  128
#define CsF  256
#define DoC  128
#define NCOLS (Bc*Mq)        // 32768
#define NBLK  256            // gemm1/gemm2 grid
#define PH   2048            // points per half (knn split)

// ---------------- scratch (device globals; no runtime allocation) -------------
__device__ __align__(16) float d_W1t[384*DoC];
__device__ __align__(16) float d_W2t[DoC*DoC];
__device__ __align__(16) float d_P  [Bc*Np*DoC];
__device__ float d_cd[Bc*Mq*6];
__device__ int   d_ci[Bc*Mq*6];
__device__ int   d_idx[Bc*Mq*3];
__device__ float d_w  [Bc*Mq*3];
__device__ __align__(16) float d_z1 [Bc*DoC*Mq];
__device__ __align__(16) float d_z2 [Bc*DoC*Mq];
__device__ float d_psum[NBLK*DoC];
__device__ float d_psq [NBLK*DoC];
__device__ float d_bn1[2*DoC];
__device__ float d_bn2[2*DoC];

// ---------------- cp.async helpers ----------------
__device__ __forceinline__ void cp16(float* s, const float* g) {
  unsigned sa = (unsigned)__cvta_generic_to_shared(s);
  asm volatile("cp.async.cg.shared.global [%0], [%1], 16;\n" :: "r"(sa), "l"(g));
}
__device__ __forceinline__ void cp_commit() { asm volatile("cp.async.commit_group;\n"); }
template<int N> __device__ __forceinline__ void cp_wait() {
  asm volatile("cp.async.wait_group %0;\n" :: "n"(N));
}

// ---------------- W transpose ----------------
__global__ __launch_bounds__(256) void transpose_w_kernel(
    const float* __restrict__ W1, const float* __restrict__ W2) {
  int e = blockIdx.x * 256 + threadIdx.x;
  if (e < 384*DoC) {
    int k = e >> 7, o = e & 127;
    d_W1t[e] = W1[o*384 + k];
  } else {
    int e2 = e - 384*DoC;
    int k = e2 >> 7, o = e2 & 127;
    d_W2t[e2] = W2[o*DoC + k];
  }
}

// ---------------- 3-NN search: split point dim in 2, float4 smem ----------------
__global__ __launch_bounds__(256) void knn_kernel(
    const float* __restrict__ xyz, const float* __restrict__ sub_xyz) {
  __shared__ float4 pts[PH];   // 32KB
  int b    = blockIdx.x >> 7;
  int half = (blockIdx.x >> 6) & 1;
  int m    = ((blockIdx.x & 63) << 8) + threadIdx.x;
  const float* sp = sub_xyz + (size_t)b * 3 * Np + half * PH;
  for (int i = threadIdx.x; i < PH; i += 256) {
    float px = sp[i], py = sp[Np + i], pz = sp[2*Np + i];
    pts[i] = make_float4(px, py, pz, fmaf(px, px, fmaf(py, py, pz*pz)));
  }
  __syncthreads();
  const float* qp = xyz + (size_t)b * 3 * Mq;
  float nx = -2.0f * qp[m], ny = -2.0f * qp[Mq + m], nz = -2.0f * qp[2*Mq + m];

  float c0 = 3.4e38f, c1 = 3.4e38f, c2 = 3.4e38f;
  int j0 = 0, j1 = 0, j2 = 0;
  #pragma unroll 8
  for (int i = 0; i < PH; i++) {
    float4 p = pts[i];
    float e = fmaf(nx, p.x, fmaf(ny, p.y, fmaf(nz, p.z, p.w)));
    if (e < c2) {
      if (e < c1) {
        c2 = c1; j2 = j1;
        if (e < c0) { c1 = c0; j1 = j0; c0 = e; j0 = i; }
        else        { c1 = e; j1 = i; }
      } else { c2 = e; j2 = i; }
    }
  }
  size_t base = ((size_t)(b * Mq + m) * 2 + half) * 3;
  int off = half * PH;
  d_cd[base + 0] = c0; d_cd[base + 1] = c1; d_cd[base + 2] = c2;
  d_ci[base + 0] = j0 + off; d_ci[base + 1] = j1 + off; d_ci[base + 2] = j2 + off;
}

// ---------------- merge 6 candidates -> final idx/weights ----------------
__global__ __launch_bounds__(256) void knn_merge_kernel(const float* __restrict__ xyz) {
  int g = blockIdx.x * 256 + threadIdx.x;   // 0..32767
  int b = g >> 14, m = g & (Mq - 1);
  const float* qp = xyz + (size_t)b * 3 * Mq;
  float qx = qp[m], qy = qp[Mq + m], qz = qp[2*Mq + m];
  float qq = fmaf(qx, qx, fmaf(qy, qy, qz*qz));
  float c0 = 3.4e38f, c1 = 3.4e38f, c2 = 3.4e38f;
  int j0 = 0, j1 = 0, j2 = 0;
  size_t base = (size_t)g * 6;
  #pragma unroll
  for (int t = 0; t < 6; t++) {            // half0 first -> stable on ties
    float e = d_cd[base + t];
    int  id = d_ci[base + t];
    if (e < c2) {
      if (e < c1) {
        c2 = c1; j2 = j1;
        if (e < c0) { c1 = c0; j1 = j0; c0 = e; j0 = id; }
        else        { c1 = e; j1 = id; }
      } else { c2 = e; j2 = id; }
    }
  }
  float d0 = fmaxf(c0 + qq, 0.0f);
  float d1 = fmaxf(c1 + qq, 0.0f);
  float d2v = fmaxf(c2 + qq, 0.0f);
  float w0 = 1.0f / (d0 + 1e-8f);
  float w1 = 1.0f / (d1 + 1e-8f);
  float w2 = 1.0f / (d2v + 1e-8f);
  float inv = 1.0f / (w0 + w1 + w2);
  d_idx[g*3 + 0] = j0; d_idx[g*3 + 1] = j1; d_idx[g*3 + 2] = j2;
  d_w[g*3 + 0] = w0*inv; d_w[g*3 + 1] = w1*inv; d_w[g*3 + 2] = w2*inv;
}

// ---------------- P = W1[:,128:384] @ sub_x, stored [b][n][o]; 64-col tiles ----------------
__global__ __launch_bounds__(256) void gemmP_kernel(const float* __restrict__ sub_x) {
  extern __shared__ float smem[];
  float* Ws = smem;            // [2][32][128]
  float* Xs = smem + 8192;     // [2][32][64]
  int b  = blockIdx.x >> 6;
  int n0 = (blockIdx.x & 63) << 6;
  int tid = threadIdx.x;
  int tx = tid & 15, ty = tid >> 4;
  const float* xb = sub_x + (size_t)b * CsF * Np;
  float acc[8][4];
  #pragma unroll
  for (int i = 0; i < 8; i++)
    #pragma unroll
    for (int j = 0; j < 4; j++) acc[i][j] = 0.0f;

  auto load_chunk = [&](int kc, int s) {
    float* Wd = Ws + s * 4096;
    float* Xd = Xs + s * 2048;
    #pragma unroll
    for (int k = 0; k < 4; k++) {
      int e4 = tid + k*256, kk = e4 >> 5, c = (e4 & 31) << 2;
      cp16(Wd + kk*128 + c, d_W1t + (size_t)(Cin + kc + kk)*DoC + c);
    }
    #pragma unroll
    for (int k = 0; k < 2; k++) {
      int e4 = tid + k*256, kk = e4 >> 4, c = (e4 & 15) << 2;
      cp16(Xd + kk*64 + c, xb + (size_t)(kc + kk)*Np + n0 + c);
    }
  };
  load_chunk(0, 0); cp_commit();
  for (int ch = 0; ch < 8; ch++) {
    if (ch < 7) { load_chunk((ch+1)*32, (ch+1)&1); cp_commit(); cp_wait<1>(); }
    else        { cp_wait<0>(); }
    __syncthreads();
    const float* Wp = Ws + (ch & 1) * 4096;
    const float* Xp = Xs + (ch & 1) * 2048;
    #pragma unroll
    for (int kk = 0; kk < 32; kk++) {
      float a[8], bb[4];
      *(float4*)&a[0]  = *(const float4*)(Wp + kk*128 + ty*8);
      *(float4*)&a[4]  = *(const float4*)(Wp + kk*128 + ty*8 + 4);
      *(float4*)&bb[0] = *(const float4*)(Xp + kk*64 + tx*4);
      #pragma unroll
      for (int i = 0; i < 8; i++)
        #pragma unroll
        for (int j = 0; j < 4; j++) acc[i][j] = fmaf(a[i], bb[j], acc[i][j]);
    }
    __syncthreads();
  }
  #pragma unroll
  for (int j = 0; j < 4; j++) {
    float* dst = &d_P[(((size_t)b * Np) + n0 + tx*4 + j) * DoC + ty*8];
    *(float4*)dst       = make_float4(acc[0][j], acc[1][j], acc[2][j], acc[3][j]);
    *(float4*)(dst + 4) = make_float4(acc[4][j], acc[5][j], acc[6][j], acc[7][j]);
  }
}

// ---------------- z1 = W1a @ x + gather(P), + shfl block stats ----------------
__global__ __launch_bounds__(256, 2) void gemm1_kernel(const float* __restrict__ x) {
  extern __shared__ float smem[];
  float* Ws   = smem;                    // [2][32][128]
  float* Xs   = smem + 8192;             // [2][32][128]
  int*   sidx = (int*)(smem + 16384);    // 384
  float* sw   = smem + 16768;            // 384
  int n0g = blockIdx.x << 7;
  int b   = n0g >> 14;
  int m0  = n0g & (Mq - 1);
  int tid = threadIdx.x;
  int tx = tid & 15, ty = tid >> 4;
  const float* xb = x + (size_t)b * Cin * Mq;
  float acc[8][8];
  #pragma unroll
  for (int i = 0; i < 8; i++)
    #pragma unroll
    for (int j = 0; j < 8; j++) acc[i][j] = 0.0f;

  auto load_chunk = [&](int kc, int s) {
    float* Wd = Ws + s * 4096;
    float* Xd = Xs + s * 4096;
    #pragma unroll
    for (int k = 0; k < 4; k++) {
      int e4 = tid + k*256, kk = e4 >> 5, c = (e4 & 31) << 2;
      cp16(Wd + kk*128 + c, d_W1t + (size_t)(kc + kk)*DoC + c);
      cp16(Xd + kk*128 + c, xb + (size_t)(kc + kk)*Mq + m0 + c);
    }
  };
  load_chunk(0, 0); cp_commit();
  for (int ch = 0; ch < 4; ch++) {
    if (ch < 3) { load_chunk((ch+1)*32, (ch+1)&1); cp_commit(); cp_wait<1>(); }
    else        { cp_wait<0>(); }
    __syncthreads();
    const float* Wp = Ws + (ch & 1) * 4096;
    const float* Xp = Xs + (ch & 1) * 4096;
    #pragma unroll
    for (int kk = 0; kk < 32; kk++) {
      float a[8], bb[8];
      *(float4*)&a[0]  = *(const float4*)(Wp + kk*128 + ty*8);
      *(float4*)&a[4]  = *(const float4*)(Wp + kk*128 + ty*8 + 4);
      *(float4*)&bb[0] = *(const float4*)(Xp + kk*128 + tx*8);
      *(float4*)&bb[4] = *(const float4*)(Xp + kk*128 + tx*8 + 4);
      #pragma unroll
      for (int i = 0; i < 8; i++)
        #pragma unroll
        for (int j = 0; j < 8; j++) acc[i][j] = fmaf(a[i], bb[j], acc[i][j]);
    }
    __syncthreads();
  }

  // gather-interpolate through P
  {
    size_t cb = ((size_t)(b * Mq + m0)) * 3;
    for (int e = tid; e < 384; e += 256) { sidx[e] = d_idx[cb + e]; sw[e] = d_w[cb + e]; }
  }
  __syncthreads();
  #pragma unroll
  for (int j = 0; j < 8; j++) {
    int col = tx*8 + j;
    #pragma unroll
    for (int t = 0; t < 3; t++) {
      int   id = sidx[col*3 + t];
      float wt = sw  [col*3 + t];
      const float* pr = &d_P[(((size_t)b * Np) + id) * DoC + ty*8];
      float4 p0 = *(const float4*)pr;
      float4 p1 = *(const float4*)(pr + 4);
      acc[0][j] = fmaf(wt, p0.x, acc[0][j]);
      acc[1][j] = fmaf(wt, p0.y, acc[1][j]);
      acc[2][j] = fmaf(wt, p0.z, acc[2][j]);
      acc[3][j] = fmaf(wt, p0.w, acc[3][j]);
      acc[4][j] = fmaf(wt, p1.x, acc[4][j]);
      acc[5][j] = fmaf(wt, p1.y, acc[5][j]);
      acc[6][j] = fmaf(wt, p1.z, acc[6][j]);
      acc[7][j] = fmaf(wt, p1.w, acc[7][j]);
    }
  }

  // store z1
  #pragma unroll
  for (int i = 0; i < 8; i++) {
    float* dst = &d_z1[((size_t)(b * DoC + ty*8 + i)) * Mq + m0 + tx*8];
    *(float4*)dst       = make_float4(acc[i][0], acc[i][1], acc[i][2], acc[i][3]);
    *(float4*)(dst + 4) = make_float4(acc[i][4], acc[i][5], acc[i][6], acc[i][7]);
  }

  // shfl-butterfly stats over the 16 tx lanes (offsets <=8 stay in 16-lane halves)
  float s8[8], q8[8];
  #pragma unroll
  for (int i = 0; i < 8; i++) {
    float s = 0.0f, q = 0.0f;
    #pragma unroll
    for (int j = 0; j < 8; j++) { s += acc[i][j]; q += acc[i][j]*acc[i][j]; }
    s8[i] = s; q8[i] = q;
  }
  #pragma unroll
  for (int off = 8; off >= 1; off >>= 1) {
    #pragma unroll
    for (int i = 0; i < 8; i++) {
      s8[i] += __shfl_xor_sync(0xffffffffu, s8[i], off);
      q8[i] += __shfl_xor_sync(0xffffffffu, q8[i], off);
    }
  }
  if (tx == 0) {
    #pragma unroll
    for (int i = 0; i < 8; i++) {
      d_psum[blockIdx.x * DoC + ty*8 + i] = s8[i];
      d_psq [blockIdx.x * DoC + ty*8 + i] = q8[i];
    }
  }
}

// ---------------- BN finalize ----------------
__global__ void bn_finalize_kernel(const float* __restrict__ g,
                                   const float* __restrict__ bias, int which) {
  __shared__ float ss[512], sq[512];
  int tid = threadIdx.x;               // 512
  int ch = tid & 127, part = tid >> 7;
  float s = 0.0f, q = 0.0f;
  for (int blk = part; blk < NBLK; blk += 4) {
    s += d_psum[blk * DoC + ch];
    q += d_psq [blk * DoC + ch];
  }
  ss[tid] = s; sq[tid] = q;
  __syncthreads();
  if (tid < 128) {
    float S = ss[tid] + ss[tid+128] + ss[tid+256] + ss[tid+384];
    float Q = sq[tid] + sq[tid+128] + sq[tid+256] + sq[tid+384];
    const float invN = 1.0f / (float)NCOLS;
    float mean = S * invN;
    float var  = Q * invN - mean * mean;
    float rstd = rsqrtf(var + 1e-5f);
    float a = g[tid] * rstd;
    float d = bias[tid] - mean * a;
    float* ab = which ? d_bn2 : d_bn1;
    ab[tid] = a; ab[DoC + tid] = d;
  }
}

// ---------------- z2 = W2 @ relu(bn1(z1)), + shfl block stats ----------------
__global__ __launch_bounds__(256, 2) void gemm2_kernel() {
  extern __shared__ float smem[];
  float* Ws  = smem;             // [2][32][128]
  float* Xs  = smem + 8192;      // [2][32][128]
  float* sa  = smem + 16384;     // 128
  float* sd  = smem + 16512;     // 128
  int n0g = blockIdx.x << 7;
  int b   = n0g >> 14;
  int m0  = n0g & (Mq - 1);
  int tid = threadIdx.x;
  int tx = tid & 15, ty = tid >> 4;
  if (tid < 128) { sa[tid] = d_bn1[tid]; sd[tid] = d_bn1[DoC + tid]; }
  const float* zb = d_z1 + (size_t)b * DoC * Mq;
  float acc[8][8];
  #pragma unroll
  for (int i = 0; i < 8; i++)
    #pragma unroll
    for (int j = 0; j < 8; j++) acc[i][j] = 0.0f;

  auto load_chunk = [&](int kc, int s) {
    float* Wd = Ws + s * 4096;
    float* Xd = Xs + s * 4096;
    #pragma unroll
    for (int k = 0; k < 4; k++) {
      int e4 = tid + k*256, kk = e4 >> 5, c = (e4 & 31) << 2;
      cp16(Wd + kk*128 + c, d_W2t + (size_t)(kc + kk)*DoC + c);
      cp16(Xd + kk*128 + c, zb + (size_t)(kc + kk)*Mq + m0 + c);
    }
  };
  load_chunk(0, 0); cp_commit();
  for (int ch = 0; ch < 4; ch++) {
    if (ch < 3) { load_chunk((ch+1)*32, (ch+1)&1); cp_commit(); cp_wait<1>(); }
    else        { cp_wait<0>(); }
    __syncthreads();
    float* Xp = Xs + (ch & 1) * 4096;
    const float* Wp = Ws + (ch & 1) * 4096;
    int kc = ch * 32;
    // apply relu(bn1(.)) in place on this chunk
    #pragma unroll
    for (int k = 0; k < 4; k++) {
      int e4 = tid + k*256, kk = e4 >> 5, c = (e4 & 31) << 2;
      float A = sa[kc + kk], D = sd[kc + kk];
      float4 v = *(float4*)(Xp + kk*128 + c);
      v.x = fmaxf(fmaf(A, v.x, D), 0.0f);
      v.y = fmaxf(fmaf(A, v.y, D), 0.0f);
      v.z = fmaxf(fmaf(A, v.z, D), 0.0f);
      v.w = fmaxf(fmaf(A, v.w, D), 0.0f);
      *(float4*)(Xp + kk*128 + c) = v;
    }
    __syncthreads();
    #pragma unroll
    for (int kk = 0; kk < 32; kk++) {
      float a[8], bb[8];
      *(float4*)&a[0]  = *(const float4*)(Wp + kk*128 + ty*8);
      *(float4*)&a[4]  = *(const float4*)(Wp + kk*128 + ty*8 + 4);
      *(float4*)&bb[0] = *(const float4*)(Xp + kk*128 + tx*8);
      *(float4*)&bb[4] = *(const float4*)(Xp + kk*128 + tx*8 + 4);
      #pragma unroll
      for (int i = 0; i < 8; i++)
        #pragma unroll
        for (int j = 0; j < 8; j++) acc[i][j] = fmaf(a[i], bb[j], acc[i][j]);
    }
    __syncthreads();
  }

  #pragma unroll
  for (int i = 0; i < 8; i++) {
    float* dst = &d_z2[((size_t)(b * DoC + ty*8 + i)) * Mq + m0 + tx*8];
    *(float4*)dst       = make_float4(acc[i][0], acc[i][1], acc[i][2], acc[i][3]);
    *(float4*)(dst + 4) = make_float4(acc[i][4], acc[i][5], acc[i][6], acc[i][7]);
  }

  float s8[8], q8[8];
  #pragma unroll
  for (int i = 0; i < 8; i++) {
    float s = 0.0f, q = 0.0f;
    #pragma unroll
    for (int j = 0; j < 8; j++) { s += acc[i][j]; q += acc[i][j]*acc[i][j]; }
    s8[i] = s; q8[i] = q;
  }
  #pragma unroll
  for (int off = 8; off >= 1; off >>= 1) {
    #pragma unroll
    for (int i = 0; i < 8; i++) {
      s8[i] += __shfl_xor_sync(0xffffffffu, s8[i], off);
      q8[i] += __shfl_xor_sync(0xffffffffu, q8[i], off);
    }
  }
  if (tx == 0) {
    #pragma unroll
    for (int i = 0; i < 8; i++) {
      d_psum[blockIdx.x * DoC + ty*8 + i] = s8[i];
      d_psq [blockIdx.x * DoC + ty*8 + i] = q8[i];
    }
  }
}

// ---------------- out = relu(bn2(z2)) ----------------
__global__ __launch_bounds__(256) void final_kernel(float* __restrict__ out) {
  int e4 = blockIdx.x * 256 + threadIdx.x;   // float4 index
  int ch = (e4 >> 12) & 127;
  float a = d_bn2[ch], d = d_bn2[DoC + ch];
  float4 v = *((const float4*)d_z2 + e4);
  v.x = fmaxf(fmaf(a, v.x, d), 0.0f);
  v.y = fmaxf(fmaf(a, v.y, d), 0.0f);
  v.z = fmaxf(fmaf(a, v.z, d), 0.0f);
  v.w = fmaxf(fmaf(a, v.w, d), 0.0f);
  *((float4*)out + e4) = v;
}

// ---------------- launch ----------------
extern "C" void kernel_launch(void* const* d_in, const int* in_sizes, int n_in,
                              void* d_out, int out_size) {
  const float* x       = (const float*)d_in[0];
  const float* xyz     = (const float*)d_in[1];
  const float* sub_x   = (const float*)d_in[2];
  const float* sub_xyz = (const float*)d_in[3];
  const float* W1      = (const float*)d_in[4];
  const float* g1      = (const float*)d_in[5];
  const float* b1      = (const float*)d_in[6];
  const float* W2      = (const float*)d_in[7];
  const float* g2      = (const float*)d_in[8];
  const float* b2      = (const float*)d_in[9];
  float* out = (float*)d_out;

  const int smemP = 49152;                    // Ws+Xs (12288 floats)
  const int smem1 = (16384 + 768) * 4;        // 68608: tiles + sidx/sw
  const int smem2 = (16384 + 256) * 4;        // 66560: tiles + sa/sd
  cudaFuncSetAttribute(gemmP_kernel, cudaFuncAttributeMaxDynamicSharedMemorySize, smemP);
  cudaFuncSetAttribute(gemm1_kernel, cudaFuncAttributeMaxDynamicSharedMemorySize, smem1);
  cudaFuncSetAttribute(gemm2_kernel, cudaFuncAttributeMaxDynamicSharedMemorySize, smem2);

  transpose_w_kernel<<<256, 256>>>(W1, W2);
  knn_kernel<<<256, 256>>>(xyz, sub_xyz);
  knn_merge_kernel<<<128, 256>>>(xyz);
  gemmP_kernel<<<128, 256, smemP>>>(sub_x);
  gemm1_kernel<<<256, 256, smem1>>>(x);
  bn_finalize_kernel<<<1, 512>>>(g1, b1, 0);
  gemm2_kernel<<<256, 256, smem2>>>();
  bn_finalize_kernel<<<1, 512>>>(g2, b2, 1);
  final_kernel<<<4096, 256>>>(out);
}

// round 10
// speedup vs baseline: 1.2813x; 1.0312x over previous
#include <cuda_runtime.h>

#define Bc   2
#define Mq   16384
#define Np   4096
#define Cin  128
#define CsF  256
#define DoC  128
#define NCOLS (Bc*Mq)        // 32768
#define NBLK  256            // gemm1/gemm2 grid
#define PH   2048            // points per half (knn split)

// ---------------- scratch (device globals; no runtime allocation) -------------
__device__ __align__(16) float d_W1t[384*DoC];
__device__ __align__(16) float d_W2t[DoC*DoC];
__device__ __align__(16) float d_P  [Bc*Np*DoC];
__device__ float d_cd[Bc*Mq*6];
__device__ int   d_ci[Bc*Mq*6];
__device__ __align__(16) float d_z1 [Bc*DoC*Mq];
__device__ __align__(16) float d_z2 [Bc*DoC*Mq];
__device__ float d_psum[NBLK*DoC];
__device__ float d_psq [NBLK*DoC];
__device__ float d_bn1[2*DoC];
__device__ float d_bn2[2*DoC];

// ---------------- cp.async helpers ----------------
__device__ __forceinline__ void cp16(float* s, const float* g) {
  unsigned sa = (unsigned)__cvta_generic_to_shared(s);
  asm volatile("cp.async.cg.shared.global [%0], [%1], 16;\n" :: "r"(sa), "l"(g));
}
__device__ __forceinline__ void cp_commit() { asm volatile("cp.async.commit_group;\n"); }
template<int N> __device__ __forceinline__ void cp_wait() {
  asm volatile("cp.async.wait_group %0;\n" :: "n"(N));
}

// ---------------- W transpose ----------------
__global__ __launch_bounds__(256) void transpose_w_kernel(
    const float* __restrict__ W1, const float* __restrict__ W2) {
  int e = blockIdx.x * 256 + threadIdx.x;
  if (e < 384*DoC) {
    int k = e >> 7, o = e & 127;
    d_W1t[e] = W1[o*384 + k];
  } else {
    int e2 = e - 384*DoC;
    int k = e2 >> 7, o = e2 & 127;
    d_W2t[e2] = W2[o*DoC + k];
  }
}

// ---------------- fused: knn (blocks 0..255) + gemmP (blocks 256..383) ----------------
// knn: split point dim in 2, float4 smem, score e = |p|^2 - 2 q.p
// gemmP: P = W1[:,128:384] @ sub_x, stored [b][n][o]; 128o x 64n tiles
__global__ __launch_bounds__(256) void knn_gemmP_kernel(
    const float* __restrict__ xyz, const float* __restrict__ sub_xyz,
    const float* __restrict__ sub_x) {
  extern __shared__ float smem[];
  int bx = blockIdx.x;
  int tid = threadIdx.x;

  if (bx < 256) {
    // ---------------- knn role ----------------
    float4* pts = (float4*)smem;   // 32KB
    int b    = bx >> 7;
    int half = (bx >> 6) & 1;
    int m    = ((bx & 63) << 8) + tid;
    const float* sp = sub_xyz + (size_t)b * 3 * Np + half * PH;
    for (int i = tid; i < PH; i += 256) {
      float px = sp[i], py = sp[Np + i], pz = sp[2*Np + i];
      pts[i] = make_float4(px, py, pz, fmaf(px, px, fmaf(py, py, pz*pz)));
    }
    __syncthreads();
    const float* qp = xyz + (size_t)b * 3 * Mq;
    float nx = -2.0f * qp[m], ny = -2.0f * qp[Mq + m], nz = -2.0f * qp[2*Mq + m];

    float c0 = 3.4e38f, c1 = 3.4e38f, c2 = 3.4e38f;
    int j0 = 0, j1 = 0, j2 = 0;
    #pragma unroll 8
    for (int i = 0; i < PH; i++) {
      float4 p = pts[i];
      float e = fmaf(nx, p.x, fmaf(ny, p.y, fmaf(nz, p.z, p.w)));
      if (e < c2) {
        if (e < c1) {
          c2 = c1; j2 = j1;
          if (e < c0) { c1 = c0; j1 = j0; c0 = e; j0 = i; }
          else        { c1 = e; j1 = i; }
        } else { c2 = e; j2 = i; }
      }
    }
    size_t base = ((size_t)(b * Mq + m) * 2 + half) * 3;
    int off = half * PH;
    d_cd[base + 0] = c0; d_cd[base + 1] = c1; d_cd[base + 2] = c2;
    d_ci[base + 0] = j0 + off; d_ci[base + 1] = j1 + off; d_ci[base + 2] = j2 + off;
    return;
  }

  // ---------------- gemmP role ----------------
  int bxp = bx - 256;                 // 0..127
  float* Ws = smem;                   // [2][32][128]
  float* Xs = smem + 8192;            // [2][32][64]
  int b  = bxp >> 6;
  int n0 = (bxp & 63) << 6;
  int tx = tid & 15, ty = tid >> 4;
  const float* xb = sub_x + (size_t)b * CsF * Np;
  float acc[8][4];
  #pragma unroll
  for (int i = 0; i < 8; i++)
    #pragma unroll
    for (int j = 0; j < 4; j++) acc[i][j] = 0.0f;

  auto load_chunk = [&](int kc, int s) {
    float* Wd = Ws + s * 4096;
    float* Xd = Xs + s * 2048;
    #pragma unroll
    for (int k = 0; k < 4; k++) {
      int e4 = tid + k*256, kk = e4 >> 5, c = (e4 & 31) << 2;
      cp16(Wd + kk*128 + c, d_W1t + (size_t)(Cin + kc + kk)*DoC + c);
    }
    #pragma unroll
    for (int k = 0; k < 2; k++) {
      int e4 = tid + k*256, kk = e4 >> 4, c = (e4 & 15) << 2;
      cp16(Xd + kk*64 + c, xb + (size_t)(kc + kk)*Np + n0 + c);
    }
  };
  load_chunk(0, 0); cp_commit();
  for (int ch = 0; ch < 8; ch++) {
    if (ch < 7) { load_chunk((ch+1)*32, (ch+1)&1); cp_commit(); cp_wait<1>(); }
    else        { cp_wait<0>(); }
    __syncthreads();
    const float* Wp = Ws + (ch & 1) * 4096;
    const float* Xp = Xs + (ch & 1) * 2048;
    #pragma unroll
    for (int kk = 0; kk < 32; kk++) {
      float a[8], bb[4];
      *(float4*)&a[0]  = *(const float4*)(Wp + kk*128 + ty*8);
      *(float4*)&a[4]  = *(const float4*)(Wp + kk*128 + ty*8 + 4);
      *(float4*)&bb[0] = *(const float4*)(Xp + kk*64 + tx*4);
      #pragma unroll
      for (int i = 0; i < 8; i++)
        #pragma unroll
        for (int j = 0; j < 4; j++) acc[i][j] = fmaf(a[i], bb[j], acc[i][j]);
    }
    __syncthreads();
  }
  #pragma unroll
  for (int j = 0; j < 4; j++) {
    float* dst = &d_P[(((size_t)b * Np) + n0 + tx*4 + j) * DoC + ty*8];
    *(float4*)dst       = make_float4(acc[0][j], acc[1][j], acc[2][j], acc[3][j]);
    *(float4*)(dst + 4) = make_float4(acc[4][j], acc[5][j], acc[6][j], acc[7][j]);
  }
}

// ---------------- z1 = W1a @ x + gather(P) [merge inlined], + shfl stats ----------------
__global__ __launch_bounds__(256, 2) void gemm1_kernel(
    const float* __restrict__ x, const float* __restrict__ xyz) {
  extern __shared__ float smem[];
  float* Ws   = smem;                    // [2][32][128]
  float* Xs   = smem + 8192;             // [2][32][128]
  int*   sidx = (int*)(smem + 16384);    // 384
  float* sw   = smem + 16768;            // 384
  int n0g = blockIdx.x << 7;
  int b   = n0g >> 14;
  int m0  = n0g & (Mq - 1);
  int tid = threadIdx.x;
  int tx = tid & 15, ty = tid >> 4;
  const float* xb = x + (size_t)b * Cin * Mq;
  float acc[8][8];
  #pragma unroll
  for (int i = 0; i < 8; i++)
    #pragma unroll
    for (int j = 0; j < 8; j++) acc[i][j] = 0.0f;

  auto load_chunk = [&](int kc, int s) {
    float* Wd = Ws + s * 4096;
    float* Xd = Xs + s * 4096;
    #pragma unroll
    for (int k = 0; k < 4; k++) {
      int e4 = tid + k*256, kk = e4 >> 5, c = (e4 & 31) << 2;
      cp16(Wd + kk*128 + c, d_W1t + (size_t)(kc + kk)*DoC + c);
      cp16(Xd + kk*128 + c, xb + (size_t)(kc + kk)*Mq + m0 + c);
    }
  };
  load_chunk(0, 0); cp_commit();

  // inline 6-candidate merge for this block's 128 queries (threads 0..127)
  if (tid < 128) {
    int m = m0 + tid;
    const float* qp = xyz + (size_t)b * 3 * Mq;
    float qx = qp[m], qy = qp[Mq + m], qz = qp[2*Mq + m];
    float qq = fmaf(qx, qx, fmaf(qy, qy, qz*qz));
    float c0 = 3.4e38f, c1 = 3.4e38f, c2 = 3.4e38f;
    int j0 = 0, j1 = 0, j2 = 0;
    size_t base = (size_t)(b * Mq + m) * 6;
    #pragma unroll
    for (int t = 0; t < 6; t++) {          // half0 first -> stable on ties
      float e = d_cd[base + t];
      int  id = d_ci[base + t];
      if (e < c2) {
        if (e < c1) {
          c2 = c1; j2 = j1;
          if (e < c0) { c1 = c0; j1 = j0; c0 = e; j0 = id; }
          else        { c1 = e; j1 = id; }
        } else { c2 = e; j2 = id; }
      }
    }
    float d0  = fmaxf(c0 + qq, 0.0f);
    float d1  = fmaxf(c1 + qq, 0.0f);
    float d2v = fmaxf(c2 + qq, 0.0f);
    float w0 = 1.0f / (d0 + 1e-8f);
    float w1 = 1.0f / (d1 + 1e-8f);
    float w2 = 1.0f / (d2v + 1e-8f);
    float inv = 1.0f / (w0 + w1 + w2);
    sidx[tid*3 + 0] = j0; sidx[tid*3 + 1] = j1; sidx[tid*3 + 2] = j2;
    sw  [tid*3 + 0] = w0*inv; sw[tid*3 + 1] = w1*inv; sw[tid*3 + 2] = w2*inv;
  }

  for (int ch = 0; ch < 4; ch++) {
    if (ch < 3) { load_chunk((ch+1)*32, (ch+1)&1); cp_commit(); cp_wait<1>(); }
    else        { cp_wait<0>(); }
    __syncthreads();
    const float* Wp = Ws + (ch & 1) * 4096;
    const float* Xp = Xs + (ch & 1) * 4096;
    #pragma unroll
    for (int kk = 0; kk < 32; kk++) {
      float a[8], bb[8];
      *(float4*)&a[0]  = *(const float4*)(Wp + kk*128 + ty*8);
      *(float4*)&a[4]  = *(const float4*)(Wp + kk*128 + ty*8 + 4);
      *(float4*)&bb[0] = *(const float4*)(Xp + kk*128 + tx*8);
      *(float4*)&bb[4] = *(const float4*)(Xp + kk*128 + tx*8 + 4);
      #pragma unroll
      for (int i = 0; i < 8; i++)
        #pragma unroll
        for (int j = 0; j < 8; j++) acc[i][j] = fmaf(a[i], bb[j], acc[i][j]);
    }
    __syncthreads();
  }

  // gather-interpolate through P (sidx/sw written pre-mainloop; barriers above order it)
  #pragma unroll
  for (int j = 0; j < 8; j++) {
    int col = tx*8 + j;
    #pragma unroll
    for (int t = 0; t < 3; t++) {
      int   id = sidx[col*3 + t];
      float wt = sw  [col*3 + t];
      const float* pr = &d_P[(((size_t)b * Np) + id) * DoC + ty*8];
      float4 p0 = *(const float4*)pr;
      float4 p1 = *(const float4*)(pr + 4);
      acc[0][j] = fmaf(wt, p0.x, acc[0][j]);
      acc[1][j] = fmaf(wt, p0.y, acc[1][j]);
      acc[2][j] = fmaf(wt, p0.z, acc[2][j]);
      acc[3][j] = fmaf(wt, p0.w, acc[3][j]);
      acc[4][j] = fmaf(wt, p1.x, acc[4][j]);
      acc[5][j] = fmaf(wt, p1.y, acc[5][j]);
      acc[6][j] = fmaf(wt, p1.z, acc[6][j]);
      acc[7][j] = fmaf(wt, p1.w, acc[7][j]);
    }
  }

  // store z1
  #pragma unroll
  for (int i = 0; i < 8; i++) {
    float* dst = &d_z1[((size_t)(b * DoC + ty*8 + i)) * Mq + m0 + tx*8];
    *(float4*)dst       = make_float4(acc[i][0], acc[i][1], acc[i][2], acc[i][3]);
    *(float4*)(dst + 4) = make_float4(acc[i][4], acc[i][5], acc[i][6], acc[i][7]);
  }

  // shfl-butterfly stats over the 16 tx lanes
  float s8[8], q8[8];
  #pragma unroll
  for (int i = 0; i < 8; i++) {
    float s = 0.0f, q = 0.0f;
    #pragma unroll
    for (int j = 0; j < 8; j++) { s += acc[i][j]; q += acc[i][j]*acc[i][j]; }
    s8[i] = s; q8[i] = q;
  }
  #pragma unroll
  for (int off = 8; off >= 1; off >>= 1) {
    #pragma unroll
    for (int i = 0; i < 8; i++) {
      s8[i] += __shfl_xor_sync(0xffffffffu, s8[i], off);
      q8[i] += __shfl_xor_sync(0xffffffffu, q8[i], off);
    }
  }
  if (tx == 0) {
    #pragma unroll
    for (int i = 0; i < 8; i++) {
      d_psum[blockIdx.x * DoC + ty*8 + i] = s8[i];
      d_psq [blockIdx.x * DoC + ty*8 + i] = q8[i];
    }
  }
}

// ---------------- BN finalize ----------------
__global__ void bn_finalize_kernel(const float* __restrict__ g,
                                   const float* __restrict__ bias, int which) {
  __shared__ float ss[512], sq[512];
  int tid = threadIdx.x;               // 512
  int ch = tid & 127, part = tid >> 7;
  float s = 0.0f, q = 0.0f;
  for (int blk = part; blk < NBLK; blk += 4) {
    s += d_psum[blk * DoC + ch];
    q += d_psq [blk * DoC + ch];
  }
  ss[tid] = s; sq[tid] = q;
  __syncthreads();
  if (tid < 128) {
    float S = ss[tid] + ss[tid+128] + ss[tid+256] + ss[tid+384];
    float Q = sq[tid] + sq[tid+128] + sq[tid+256] + sq[tid+384];
    const float invN = 1.0f / (float)NCOLS;
    float mean = S * invN;
    float var  = Q * invN - mean * mean;
    float rstd = rsqrtf(var + 1e-5f);
    float a = g[tid] * rstd;
    float d = bias[tid] - mean * a;
    float* ab = which ? d_bn2 : d_bn1;
    ab[tid] = a; ab[DoC + tid] = d;
  }
}

// ---------------- z2 = W2 @ relu(bn1(z1)), + shfl stats ----------------
__global__ __launch_bounds__(256, 2) void gemm2_kernel() {
  extern __shared__ float smem[];
  float* Ws  = smem;             // [2][32][128]
  float* Xs  = smem + 8192;      // [2][32][128]
  float* sa  = smem + 16384;     // 128
  float* sd  = smem + 16512;     // 128
  int n0g = blockIdx.x << 7;
  int b   = n0g >> 14;
  int m0  = n0g & (Mq - 1);
  int tid = threadIdx.x;
  int tx = tid & 15, ty = tid >> 4;
  if (tid < 128) { sa[tid] = d_bn1[tid]; sd[tid] = d_bn1[DoC + tid]; }
  const float* zb = d_z1 + (size_t)b * DoC * Mq;
  float acc[8][8];
  #pragma unroll
  for (int i = 0; i < 8; i++)
    #pragma unroll
    for (int j = 0; j < 8; j++) acc[i][j] = 0.0f;

  auto load_chunk = [&](int kc, int s) {
    float* Wd = Ws + s * 4096;
    float* Xd = Xs + s * 4096;
    #pragma unroll
    for (int k = 0; k < 4; k++) {
      int e4 = tid + k*256, kk = e4 >> 5, c = (e4 & 31) << 2;
      cp16(Wd + kk*128 + c, d_W2t + (size_t)(kc + kk)*DoC + c);
      cp16(Xd + kk*128 + c, zb + (size_t)(kc + kk)*Mq + m0 + c);
    }
  };
  load_chunk(0, 0); cp_commit();
  for (int ch = 0; ch < 4; ch++) {
    if (ch < 3) { load_chunk((ch+1)*32, (ch+1)&1); cp_commit(); cp_wait<1>(); }
    else        { cp_wait<0>(); }
    __syncthreads();
    float* Xp = Xs + (ch & 1) * 4096;
    const float* Wp = Ws + (ch & 1) * 4096;
    int kc = ch * 32;
    // apply relu(bn1(.)) in place on this chunk
    #pragma unroll
    for (int k = 0; k < 4; k++) {
      int e4 = tid + k*256, kk = e4 >> 5, c = (e4 & 31) << 2;
      float A = sa[kc + kk], D = sd[kc + kk];
      float4 v = *(float4*)(Xp + kk*128 + c);
      v.x = fmaxf(fmaf(A, v.x, D), 0.0f);
      v.y = fmaxf(fmaf(A, v.y, D), 0.0f);
      v.z = fmaxf(fmaf(A, v.z, D), 0.0f);
      v.w = fmaxf(fmaf(A, v.w, D), 0.0f);
      *(float4*)(Xp + kk*128 + c) = v;
    }
    __syncthreads();
    #pragma unroll
    for (int kk = 0; kk < 32; kk++) {
      float a[8], bb[8];
      *(float4*)&a[0]  = *(const float4*)(Wp + kk*128 + ty*8);
      *(float4*)&a[4]  = *(const float4*)(Wp + kk*128 + ty*8 + 4);
      *(float4*)&bb[0] = *(const float4*)(Xp + kk*128 + tx*8);
      *(float4*)&bb[4] = *(const float4*)(Xp + kk*128 + tx*8 + 4);
      #pragma unroll
      for (int i = 0; i < 8; i++)
        #pragma unroll
        for (int j = 0; j < 8; j++) acc[i][j] = fmaf(a[i], bb[j], acc[i][j]);
    }
    __syncthreads();
  }

  #pragma unroll
  for (int i = 0; i < 8; i++) {
    float* dst = &d_z2[((size_t)(b * DoC + ty*8 + i)) * Mq + m0 + tx*8];
    *(float4*)dst       = make_float4(acc[i][0], acc[i][1], acc[i][2], acc[i][3]);
    *(float4*)(dst + 4) = make_float4(acc[i][4], acc[i][5], acc[i][6], acc[i][7]);
  }

  float s8[8], q8[8];
  #pragma unroll
  for (int i = 0; i < 8; i++) {
    float s = 0.0f, q = 0.0f;
    #pragma unroll
    for (int j = 0; j < 8; j++) { s += acc[i][j]; q += acc[i][j]*acc[i][j]; }
    s8[i] = s; q8[i] = q;
  }
  #pragma unroll
  for (int off = 8; off >= 1; off >>= 1) {
    #pragma unroll
    for (int i = 0; i < 8; i++) {
      s8[i] += __shfl_xor_sync(0xffffffffu, s8[i], off);
      q8[i] += __shfl_xor_sync(0xffffffffu, q8[i], off);
    }
  }
  if (tx == 0) {
    #pragma unroll
    for (int i = 0; i < 8; i++) {
      d_psum[blockIdx.x * DoC + ty*8 + i] = s8[i];
      d_psq [blockIdx.x * DoC + ty*8 + i] = q8[i];
    }
  }
}

// ---------------- out = relu(bn2(z2)) ----------------
__global__ __launch_bounds__(256) void final_kernel(float* __restrict__ out) {
  int e4 = blockIdx.x * 256 + threadIdx.x;   // float4 index
  int ch = (e4 >> 12) & 127;
  float a = d_bn2[ch], d = d_bn2[DoC + ch];
  float4 v = *((const float4*)d_z2 + e4);
  v.x = fmaxf(fmaf(a, v.x, d), 0.0f);
  v.y = fmaxf(fmaf(a, v.y, d), 0.0f);
  v.z = fmaxf(fmaf(a, v.z, d), 0.0f);
  v.w = fmaxf(fmaf(a, v.w, d), 0.0f);
  *((float4*)out + e4) = v;
}

// ---------------- launch ----------------
extern "C" void kernel_launch(void* const* d_in, const int* in_sizes, int n_in,
                              void* d_out, int out_size) {
  const float* x       = (const float*)d_in[0];
  const float* xyz     = (const float*)d_in[1];
  const float* sub_x   = (const float*)d_in[2];
  const float* sub_xyz = (const float*)d_in[3];
  const float* W1      = (const float*)d_in[4];
  const float* g1      = (const float*)d_in[5];
  const float* b1      = (const float*)d_in[6];
  const float* W2      = (const float*)d_in[7];
  const float* g2      = (const float*)d_in[8];
  const float* b2      = (const float*)d_in[9];
  float* out = (float*)d_out;

  const int smemF = 49152;                    // fused knn/gemmP: max(32KB knn, 48KB gemmP)
  const int smem1 = (16384 + 768) * 4;        // 68608: tiles + sidx/sw
  const int smem2 = (16384 + 256) * 4;        // 66560: tiles + sa/sd
  cudaFuncSetAttribute(knn_gemmP_kernel, cudaFuncAttributeMaxDynamicSharedMemorySize, smemF);
  cudaFuncSetAttribute(gemm1_kernel, cudaFuncAttributeMaxDynamicSharedMemorySize, smem1);
  cudaFuncSetAttribute(gemm2_kernel, cudaFuncAttributeMaxDynamicSharedMemorySize, smem2);

  transpose_w_kernel<<<256, 256>>>(W1, W2);
  knn_gemmP_kernel<<<384, 256, smemF>>>(xyz, sub_xyz, sub_x);
  gemm1_kernel<<<256, 256, smem1>>>(x, xyz);
  bn_finalize_kernel<<<1, 512>>>(g1, b1, 0);
  gemm2_kernel<<<256, 256, smem2>>>();
  bn_finalize_kernel<<<1, 512>>>(g2, b2, 1);
  final_kernel<<<4096, 256>>>(out);
}

// round 11
// speedup vs baseline: 1.4113x; 1.1015x over previous
#include <cuda_runtime.h>

#define Bc   2
#define Mq   16384
#define Np   4096
#define Cin  128
#define CsF  256
#define DoC  128
#define NCOLS (Bc*Mq)        // 32768
#define NBLK  256            // gemm1/gemm2 grid
#define PH   2048            // points per half (knn split)

// ---------------- scratch (device globals; no runtime allocation) -------------
__device__ __align__(16) float d_W1t[384*DoC];
__device__ __align__(16) float d_W2t[DoC*DoC];
__device__ __align__(16) float d_P  [Bc*Np*DoC];
__device__ float d_cd[Bc*Mq*6];
__device__ int   d_ci[Bc*Mq*6];
__device__ __align__(16) float d_z1 [Bc*DoC*Mq];
__device__ __align__(16) float d_z2 [Bc*DoC*Mq];
__device__ __align__(16) float d_psum[DoC*NBLK];   // channel-major [ch][blk]
__device__ __align__(16) float d_psq [DoC*NBLK];
__device__ float d_bn1[2*DoC];
__device__ float d_bn2[2*DoC];

// ---------------- cp.async helpers ----------------
__device__ __forceinline__ void cp16(float* s, const float* g) {
  unsigned sa = (unsigned)__cvta_generic_to_shared(s);
  asm volatile("cp.async.cg.shared.global [%0], [%1], 16;\n" :: "r"(sa), "l"(g));
}
__device__ __forceinline__ void cp_commit() { asm volatile("cp.async.commit_group;\n"); }
template<int N> __device__ __forceinline__ void cp_wait() {
  asm volatile("cp.async.wait_group %0;\n" :: "n"(N));
}

// ---------------- W transpose ----------------
__global__ __launch_bounds__(256) void transpose_w_kernel(
    const float* __restrict__ W1, const float* __restrict__ W2) {
  int e = blockIdx.x * 256 + threadIdx.x;
  if (e < 384*DoC) {
    int k = e >> 7, o = e & 127;
    d_W1t[e] = W1[o*384 + k];
  } else {
    int e2 = e - 384*DoC;
    int k = e2 >> 7, o = e2 & 127;
    d_W2t[e2] = W2[o*DoC + k];
  }
}

// ---------------- fused: knn (blocks 0..255) + gemmP (blocks 256..383) ----------------
__global__ __launch_bounds__(256) void knn_gemmP_kernel(
    const float* __restrict__ xyz, const float* __restrict__ sub_xyz,
    const float* __restrict__ sub_x) {
  extern __shared__ float smem[];
  int bx = blockIdx.x;
  int tid = threadIdx.x;

  if (bx < 256) {
    // ---------------- knn role ----------------
    float4* pts = (float4*)smem;   // 32KB
    int b    = bx >> 7;
    int half = (bx >> 6) & 1;
    int m    = ((bx & 63) << 8) + tid;
    const float* sp = sub_xyz + (size_t)b * 3 * Np + half * PH;
    for (int i = tid; i < PH; i += 256) {
      float px = sp[i], py = sp[Np + i], pz = sp[2*Np + i];
      pts[i] = make_float4(px, py, pz, fmaf(px, px, fmaf(py, py, pz*pz)));
    }
    __syncthreads();
    const float* qp = xyz + (size_t)b * 3 * Mq;
    float nx = -2.0f * qp[m], ny = -2.0f * qp[Mq + m], nz = -2.0f * qp[2*Mq + m];

    float c0 = 3.4e38f, c1 = 3.4e38f, c2 = 3.4e38f;
    int j0 = 0, j1 = 0, j2 = 0;
    #pragma unroll 8
    for (int i = 0; i < PH; i++) {
      float4 p = pts[i];
      float e = fmaf(nx, p.x, fmaf(ny, p.y, fmaf(nz, p.z, p.w)));
      if (e < c2) {
        if (e < c1) {
          c2 = c1; j2 = j1;
          if (e < c0) { c1 = c0; j1 = j0; c0 = e; j0 = i; }
          else        { c1 = e; j1 = i; }
        } else { c2 = e; j2 = i; }
      }
    }
    size_t base = ((size_t)(b * Mq + m) * 2 + half) * 3;
    int off = half * PH;
    d_cd[base + 0] = c0; d_cd[base + 1] = c1; d_cd[base + 2] = c2;
    d_ci[base + 0] = j0 + off; d_ci[base + 1] = j1 + off; d_ci[base + 2] = j2 + off;
    return;
  }

  // ---------------- gemmP role ----------------
  int bxp = bx - 256;                 // 0..127
  float* Ws = smem;                   // [2][32][128]
  float* Xs = smem + 8192;            // [2][32][64]
  int b  = bxp >> 6;
  int n0 = (bxp & 63) << 6;
  int tx = tid & 15, ty = tid >> 4;
  const float* xb = sub_x + (size_t)b * CsF * Np;
  float acc[8][4];
  #pragma unroll
  for (int i = 0; i < 8; i++)
    #pragma unroll
    for (int j = 0; j < 4; j++) acc[i][j] = 0.0f;

  auto load_chunk = [&](int kc, int s) {
    float* Wd = Ws + s * 4096;
    float* Xd = Xs + s * 2048;
    #pragma unroll
    for (int k = 0; k < 4; k++) {
      int e4 = tid + k*256, kk = e4 >> 5, c = (e4 & 31) << 2;
      cp16(Wd + kk*128 + c, d_W1t + (size_t)(Cin + kc + kk)*DoC + c);
    }
    #pragma unroll
    for (int k = 0; k < 2; k++) {
      int e4 = tid + k*256, kk = e4 >> 4, c = (e4 & 15) << 2;
      cp16(Xd + kk*64 + c, xb + (size_t)(kc + kk)*Np + n0 + c);
    }
  };
  load_chunk(0, 0); cp_commit();
  for (int ch = 0; ch < 8; ch++) {
    if (ch < 7) { load_chunk((ch+1)*32, (ch+1)&1); cp_commit(); cp_wait<1>(); }
    else        { cp_wait<0>(); }
    __syncthreads();
    const float* Wp = Ws + (ch & 1) * 4096;
    const float* Xp = Xs + (ch & 1) * 2048;
    #pragma unroll
    for (int kk = 0; kk < 32; kk++) {
      float a[8], bb[4];
      *(float4*)&a[0]  = *(const float4*)(Wp + kk*128 + ty*8);
      *(float4*)&a[4]  = *(const float4*)(Wp + kk*128 + ty*8 + 4);
      *(float4*)&bb[0] = *(const float4*)(Xp + kk*64 + tx*4);
      #pragma unroll
      for (int i = 0; i < 8; i++)
        #pragma unroll
        for (int j = 0; j < 4; j++) acc[i][j] = fmaf(a[i], bb[j], acc[i][j]);
    }
    __syncthreads();
  }
  #pragma unroll
  for (int j = 0; j < 4; j++) {
    float* dst = &d_P[(((size_t)b * Np) + n0 + tx*4 + j) * DoC + ty*8];
    *(float4*)dst       = make_float4(acc[0][j], acc[1][j], acc[2][j], acc[3][j]);
    *(float4*)(dst + 4) = make_float4(acc[4][j], acc[5][j], acc[6][j], acc[7][j]);
  }
}

// ---------------- z1 = W1a @ x + gather(P) [merge inlined], + shfl stats ----------------
__global__ __launch_bounds__(256, 2) void gemm1_kernel(
    const float* __restrict__ x, const float* __restrict__ xyz) {
  extern __shared__ float smem[];
  float* Ws   = smem;                    // [2][32][128]
  float* Xs   = smem + 8192;             // [2][32][128]
  int*   sidx = (int*)(smem + 16384);    // 384
  float* sw   = smem + 16768;            // 384
  int n0g = blockIdx.x << 7;
  int b   = n0g >> 14;
  int m0  = n0g & (Mq - 1);
  int tid = threadIdx.x;
  int tx = tid & 15, ty = tid >> 4;
  const float* xb = x + (size_t)b * Cin * Mq;
  float acc[8][8];
  #pragma unroll
  for (int i = 0; i < 8; i++)
    #pragma unroll
    for (int j = 0; j < 8; j++) acc[i][j] = 0.0f;

  auto load_chunk = [&](int kc, int s) {
    float* Wd = Ws + s * 4096;
    float* Xd = Xs + s * 4096;
    #pragma unroll
    for (int k = 0; k < 4; k++) {
      int e4 = tid + k*256, kk = e4 >> 5, c = (e4 & 31) << 2;
      cp16(Wd + kk*128 + c, d_W1t + (size_t)(kc + kk)*DoC + c);
      cp16(Xd + kk*128 + c, xb + (size_t)(kc + kk)*Mq + m0 + c);
    }
  };
  load_chunk(0, 0); cp_commit();

  // inline 6-candidate merge for this block's 128 queries (threads 0..127)
  if (tid < 128) {
    int m = m0 + tid;
    const float* qp = xyz + (size_t)b * 3 * Mq;
    float qx = qp[m], qy = qp[Mq + m], qz = qp[2*Mq + m];
    float qq = fmaf(qx, qx, fmaf(qy, qy, qz*qz));
    float c0 = 3.4e38f, c1 = 3.4e38f, c2 = 3.4e38f;
    int j0 = 0, j1 = 0, j2 = 0;
    size_t base = (size_t)(b * Mq + m) * 6;
    #pragma unroll
    for (int t = 0; t < 6; t++) {          // half0 first -> stable on ties
      float e = d_cd[base + t];
      int  id = d_ci[base + t];
      if (e < c2) {
        if (e < c1) {
          c2 = c1; j2 = j1;
          if (e < c0) { c1 = c0; j1 = j0; c0 = e; j0 = id; }
          else        { c1 = e; j1 = id; }
        } else { c2 = e; j2 = id; }
      }
    }
    float d0  = fmaxf(c0 + qq, 0.0f);
    float d1  = fmaxf(c1 + qq, 0.0f);
    float d2v = fmaxf(c2 + qq, 0.0f);
    float w0 = 1.0f / (d0 + 1e-8f);
    float w1 = 1.0f / (d1 + 1e-8f);
    float w2 = 1.0f / (d2v + 1e-8f);
    float inv = 1.0f / (w0 + w1 + w2);
    sidx[tid*3 + 0] = j0; sidx[tid*3 + 1] = j1; sidx[tid*3 + 2] = j2;
    sw  [tid*3 + 0] = w0*inv; sw[tid*3 + 1] = w1*inv; sw[tid*3 + 2] = w2*inv;
  }

  for (int ch = 0; ch < 4; ch++) {
    if (ch < 3) { load_chunk((ch+1)*32, (ch+1)&1); cp_commit(); cp_wait<1>(); }
    else        { cp_wait<0>(); }
    __syncthreads();
    const float* Wp = Ws + (ch & 1) * 4096;
    const float* Xp = Xs + (ch & 1) * 4096;
    #pragma unroll
    for (int kk = 0; kk < 32; kk++) {
      float a[8], bb[8];
      *(float4*)&a[0]  = *(const float4*)(Wp + kk*128 + ty*8);
      *(float4*)&a[4]  = *(const float4*)(Wp + kk*128 + ty*8 + 4);
      *(float4*)&bb[0] = *(const float4*)(Xp + kk*128 + tx*8);
      *(float4*)&bb[4] = *(const float4*)(Xp + kk*128 + tx*8 + 4);
      #pragma unroll
      for (int i = 0; i < 8; i++)
        #pragma unroll
        for (int j = 0; j < 8; j++) acc[i][j] = fmaf(a[i], bb[j], acc[i][j]);
    }
    __syncthreads();
  }

  // gather-interpolate through P
  #pragma unroll
  for (int j = 0; j < 8; j++) {
    int col = tx*8 + j;
    #pragma unroll
    for (int t = 0; t < 3; t++) {
      int   id = sidx[col*3 + t];
      float wt = sw  [col*3 + t];
      const float* pr = &d_P[(((size_t)b * Np) + id) * DoC + ty*8];
      float4 p0 = *(const float4*)pr;
      float4 p1 = *(const float4*)(pr + 4);
      acc[0][j] = fmaf(wt, p0.x, acc[0][j]);
      acc[1][j] = fmaf(wt, p0.y, acc[1][j]);
      acc[2][j] = fmaf(wt, p0.z, acc[2][j]);
      acc[3][j] = fmaf(wt, p0.w, acc[3][j]);
      acc[4][j] = fmaf(wt, p1.x, acc[4][j]);
      acc[5][j] = fmaf(wt, p1.y, acc[5][j]);
      acc[6][j] = fmaf(wt, p1.z, acc[6][j]);
      acc[7][j] = fmaf(wt, p1.w, acc[7][j]);
    }
  }

  // store z1
  #pragma unroll
  for (int i = 0; i < 8; i++) {
    float* dst = &d_z1[((size_t)(b * DoC + ty*8 + i)) * Mq + m0 + tx*8];
    *(float4*)dst       = make_float4(acc[i][0], acc[i][1], acc[i][2], acc[i][3]);
    *(float4*)(dst + 4) = make_float4(acc[i][4], acc[i][5], acc[i][6], acc[i][7]);
  }

  // shfl-butterfly stats over the 16 tx lanes
  float s8[8], q8[8];
  #pragma unroll
  for (int i = 0; i < 8; i++) {
    float s = 0.0f, q = 0.0f;
    #pragma unroll
    for (int j = 0; j < 8; j++) { s += acc[i][j]; q += acc[i][j]*acc[i][j]; }
    s8[i] = s; q8[i] = q;
  }
  #pragma unroll
  for (int off = 8; off >= 1; off >>= 1) {
    #pragma unroll
    for (int i = 0; i < 8; i++) {
      s8[i] += __shfl_xor_sync(0xffffffffu, s8[i], off);
      q8[i] += __shfl_xor_sync(0xffffffffu, q8[i], off);
    }
  }
  if (tx == 0) {
    #pragma unroll
    for (int i = 0; i < 8; i++) {
      d_psum[(ty*8 + i) * NBLK + blockIdx.x] = s8[i];
      d_psq [(ty*8 + i) * NBLK + blockIdx.x] = q8[i];
    }
  }
}

// ---------------- BN finalize: one block per channel, coalesced ----------------
__global__ __launch_bounds__(256) void bn_finalize_kernel(
    const float* __restrict__ g, const float* __restrict__ bias, int which) {
  __shared__ float ss[256], sq[256];
  int ch = blockIdx.x;       // 128 blocks
  int tid = threadIdx.x;     // 256 = NBLK
  ss[tid] = d_psum[ch * NBLK + tid];
  sq[tid] = d_psq [ch * NBLK + tid];
  __syncthreads();
  #pragma unroll
  for (int off = 128; off >= 1; off >>= 1) {
    if (tid < off) { ss[tid] += ss[tid + off]; sq[tid] += sq[tid + off]; }
    __syncthreads();
  }
  if (tid == 0) {
    const float invN = 1.0f / (float)NCOLS;
    float mean = ss[0] * invN;
    float var  = sq[0] * invN - mean * mean;
    float rstd = rsqrtf(var + 1e-5f);
    float a = g[ch] * rstd;
    float d = bias[ch] - mean * a;
    float* ab = which ? d_bn2 : d_bn1;
    ab[ch] = a; ab[DoC + ch] = d;
  }
}

// ---------------- z2 = W2 @ relu(bn1(z1)), + shfl stats ----------------
__global__ __launch_bounds__(256, 2) void gemm2_kernel() {
  extern __shared__ float smem[];
  float* Ws  = smem;             // [2][32][128]
  float* Xs  = smem + 8192;      // [2][32][128]
  float* sa  = smem + 16384;     // 128
  float* sd  = smem + 16512;     // 128
  int n0g = blockIdx.x << 7;
  int b   = n0g >> 14;
  int m0  = n0g & (Mq - 1);
  int tid = threadIdx.x;
  int tx = tid & 15, ty = tid >> 4;
  if (tid < 128) { sa[tid] = d_bn1[tid]; sd[tid] = d_bn1[DoC + tid]; }
  const float* zb = d_z1 + (size_t)b * DoC * Mq;
  float acc[8][8];
  #pragma unroll
  for (int i = 0; i < 8; i++)
    #pragma unroll
    for (int j = 0; j < 8; j++) acc[i][j] = 0.0f;

  auto load_chunk = [&](int kc, int s) {
    float* Wd = Ws + s * 4096;
    float* Xd = Xs + s * 4096;
    #pragma unroll
    for (int k = 0; k < 4; k++) {
      int e4 = tid + k*256, kk = e4 >> 5, c = (e4 & 31) << 2;
      cp16(Wd + kk*128 + c, d_W2t + (size_t)(kc + kk)*DoC + c);
      cp16(Xd + kk*128 + c, zb + (size_t)(kc + kk)*Mq + m0 + c);
    }
  };
  load_chunk(0, 0); cp_commit();
  for (int ch = 0; ch < 4; ch++) {
    if (ch < 3) { load_chunk((ch+1)*32, (ch+1)&1); cp_commit(); cp_wait<1>(); }
    else        { cp_wait<0>(); }
    __syncthreads();
    float* Xp = Xs + (ch & 1) * 4096;
    const float* Wp = Ws + (ch & 1) * 4096;
    int kc = ch * 32;
    // apply relu(bn1(.)) in place on this chunk
    #pragma unroll
    for (int k = 0; k < 4; k++) {
      int e4 = tid + k*256, kk = e4 >> 5, c = (e4 & 31) << 2;
      float A = sa[kc + kk], D = sd[kc + kk];
      float4 v = *(float4*)(Xp + kk*128 + c);
      v.x = fmaxf(fmaf(A, v.x, D), 0.0f);
      v.y = fmaxf(fmaf(A, v.y, D), 0.0f);
      v.z = fmaxf(fmaf(A, v.z, D), 0.0f);
      v.w = fmaxf(fmaf(A, v.w, D), 0.0f);
      *(float4*)(Xp + kk*128 + c) = v;
    }
    __syncthreads();
    #pragma unroll
    for (int kk = 0; kk < 32; kk++) {
      float a[8], bb[8];
      *(float4*)&a[0]  = *(const float4*)(Wp + kk*128 + ty*8);
      *(float4*)&a[4]  = *(const float4*)(Wp + kk*128 + ty*8 + 4);
      *(float4*)&bb[0] = *(const float4*)(Xp + kk*128 + tx*8);
      *(float4*)&bb[4] = *(const float4*)(Xp + kk*128 + tx*8 + 4);
      #pragma unroll
      for (int i = 0; i < 8; i++)
        #pragma unroll
        for (int j = 0; j < 8; j++) acc[i][j] = fmaf(a[i], bb[j], acc[i][j]);
    }
    __syncthreads();
  }

  #pragma unroll
  for (int i = 0; i < 8; i++) {
    float* dst = &d_z2[((size_t)(b * DoC + ty*8 + i)) * Mq + m0 + tx*8];
    *(float4*)dst       = make_float4(acc[i][0], acc[i][1], acc[i][2], acc[i][3]);
    *(float4*)(dst + 4) = make_float4(acc[i][4], acc[i][5], acc[i][6], acc[i][7]);
  }

  float s8[8], q8[8];
  #pragma unroll
  for (int i = 0; i < 8; i++) {
    float s = 0.0f, q = 0.0f;
    #pragma unroll
    for (int j = 0; j < 8; j++) { s += acc[i][j]; q += acc[i][j]*acc[i][j]; }
    s8[i] = s; q8[i] = q;
  }
  #pragma unroll
  for (int off = 8; off >= 1; off >>= 1) {
    #pragma unroll
    for (int i = 0; i < 8; i++) {
      s8[i] += __shfl_xor_sync(0xffffffffu, s8[i], off);
      q8[i] += __shfl_xor_sync(0xffffffffu, q8[i], off);
    }
  }
  if (tx == 0) {
    #pragma unroll
    for (int i = 0; i < 8; i++) {
      d_psum[(ty*8 + i) * NBLK + blockIdx.x] = s8[i];
      d_psq [(ty*8 + i) * NBLK + blockIdx.x] = q8[i];
    }
  }
}

// ---------------- out = relu(bn2(z2)) ----------------
__global__ __launch_bounds__(256) void final_kernel(float* __restrict__ out) {
  int e4 = blockIdx.x * 256 + threadIdx.x;   // float4 index
  int ch = (e4 >> 12) & 127;
  float a = d_bn2[ch], d = d_bn2[DoC + ch];
  float4 v = *((const float4*)d_z2 + e4);
  v.x = fmaxf(fmaf(a, v.x, d), 0.0f);
  v.y = fmaxf(fmaf(a, v.y, d), 0.0f);
  v.z = fmaxf(fmaf(a, v.z, d), 0.0f);
  v.w = fmaxf(fmaf(a, v.w, d), 0.0f);
  *((float4*)out + e4) = v;
}

// ---------------- launch ----------------
extern "C" void kernel_launch(void* const* d_in, const int* in_sizes, int n_in,
                              void* d_out, int out_size) {
  const float* x       = (const float*)d_in[0];
  const float* xyz     = (const float*)d_in[1];
  const float* sub_x   = (const float*)d_in[2];
  const float* sub_xyz = (const float*)d_in[3];
  const float* W1      = (const float*)d_in[4];
  const float* g1      = (const float*)d_in[5];
  const float* b1      = (const float*)d_in[6];
  const float* W2      = (const float*)d_in[7];
  const float* g2      = (const float*)d_in[8];
  const float* b2      = (const float*)d_in[9];
  float* out = (float*)d_out;

  const int smemF = 49152;
  const int smem1 = (16384 + 768) * 4;
  const int smem2 = (16384 + 256) * 4;
  cudaFuncSetAttribute(knn_gemmP_kernel, cudaFuncAttributeMaxDynamicSharedMemorySize, smemF);
  cudaFuncSetAttribute(gemm1_kernel, cudaFuncAttributeMaxDynamicSharedMemorySize, smem1);
  cudaFuncSetAttribute(gemm2_kernel, cudaFuncAttributeMaxDynamicSharedMemorySize, smem2);

  transpose_w_kernel<<<256, 256>>>(W1, W2);
  knn_gemmP_kernel<<<384, 256, smemF>>>(xyz, sub_xyz, sub_x);
  gemm1_kernel<<<256, 256, smem1>>>(x, xyz);
  bn_finalize_kernel<<<128, 256>>>(g1, b1, 0);
  gemm2_kernel<<<256, 256, smem2>>>();
  bn_finalize_kernel<<<128, 256>>>(g2, b2, 1);
  final_kernel<<<4096, 256>>>(out);
}